// round 1
// baseline (speedup 1.0000x reference)
#include <cuda_runtime.h>
#include <math.h>

// Problem constants (fixed shapes from reference)
#define T_TOK 4096
#define DDIM  1024
#define NEXP  8
#define FDIM  512
#define FSDIM 1024
#define KDOWN (NEXP * FDIM + FSDIM)   // 5120
#define TOPK  6

// Scratch (device-global: no runtime allocation allowed)
__device__ float g_W[T_TOK * NEXP];                    // routing weights (0 if not selected)
__device__ float g_H[(size_t)T_TOK * KDOWN];           // concatenated expert hidden states

// ---------------------------------------------------------------------------
// Router: scores = softmax(x @ router_w), keep top-6 weights, zero the rest.
// One warp per token.
// ---------------------------------------------------------------------------
__global__ void router_kernel(const float* __restrict__ x,
                              const float* __restrict__ rw) {
    int gw = (blockIdx.x * blockDim.x + threadIdx.x) >> 5;
    int lane = threadIdx.x & 31;
    if (gw >= T_TOK) return;
    const float* xr = x + (size_t)gw * DDIM;

    float acc[NEXP];
#pragma unroll
    for (int e = 0; e < NEXP; e++) acc[e] = 0.f;

    for (int d = lane; d < DDIM; d += 32) {
        float xv = xr[d];
        const float4* r4 = reinterpret_cast<const float4*>(rw + (size_t)d * NEXP);
        float4 r0 = r4[0], r1 = r4[1];
        acc[0] = fmaf(xv, r0.x, acc[0]);
        acc[1] = fmaf(xv, r0.y, acc[1]);
        acc[2] = fmaf(xv, r0.z, acc[2]);
        acc[3] = fmaf(xv, r0.w, acc[3]);
        acc[4] = fmaf(xv, r1.x, acc[4]);
        acc[5] = fmaf(xv, r1.y, acc[5]);
        acc[6] = fmaf(xv, r1.z, acc[6]);
        acc[7] = fmaf(xv, r1.w, acc[7]);
    }
#pragma unroll
    for (int off = 16; off > 0; off >>= 1) {
#pragma unroll
        for (int e = 0; e < NEXP; e++)
            acc[e] += __shfl_xor_sync(0xffffffffu, acc[e], off);
    }
    if (lane == 0) {
        float m = acc[0];
#pragma unroll
        for (int e = 1; e < NEXP; e++) m = fmaxf(m, acc[e]);
        float p[NEXP], s = 0.f;
#pragma unroll
        for (int e = 0; e < NEXP; e++) { p[e] = expf(acc[e] - m); s += p[e]; }
        float inv = 1.f / s;
#pragma unroll
        for (int e = 0; e < NEXP; e++) p[e] *= inv;
        // rank by descending score, ties -> lower index wins (matches jax top_k)
#pragma unroll
        for (int e = 0; e < NEXP; e++) {
            int rank = 0;
#pragma unroll
            for (int e2 = 0; e2 < NEXP; e2++)
                rank += (p[e2] > p[e] || (p[e2] == p[e] && e2 < e)) ? 1 : 0;
            g_W[gw * NEXP + e] = (rank < TOPK) ? p[e] : 0.f;
        }
    }
}

// ---------------------------------------------------------------------------
// Fused gate+up GEMM:  H[t, hcol_base + z*fdim + n] =
//     silu(X@Wg[z]) * (X@Wu[z]) * (scaled ? g_W[t, z] : 1)
// Tile: BM=128 x BN=64 x BK=16, 256 threads, 8x4 per-thread micro-tile
// (two accumulator sets: gate and up).
// ---------------------------------------------------------------------------
__global__ __launch_bounds__(256, 2)
void gateup_kernel(const float* __restrict__ X,
                   const float* __restrict__ Wg_all,
                   const float* __restrict__ Wu_all,
                   int fdim, int hcol_base, int scaled) {
    const int e  = blockIdx.z;
    const float* Wg = Wg_all + (size_t)e * DDIM * fdim;
    const float* Wu = Wu_all + (size_t)e * DDIM * fdim;
    const int bm = blockIdx.y * 128;
    const int bn = blockIdx.x * 64;
    const int tid = threadIdx.x;

    __shared__ float As[16][132];   // [k][m], padded
    __shared__ float Bgs[16][64];   // [k][n]
    __shared__ float Bus[16][64];

    const int tx = tid & 15, ty = tid >> 4;
    const int m0 = ty * 8, n0 = tx * 4;

    float accG[8][4], accU[8][4];
#pragma unroll
    for (int i = 0; i < 8; i++)
#pragma unroll
        for (int j = 0; j < 4; j++) { accG[i][j] = 0.f; accU[i][j] = 0.f; }

    // load-index precompute
    const int am0 = tid >> 2;            // 0..63  (m for pa0; +64 for pa1)
    const int akc = (tid & 3) * 4;       // k chunk within BK
    const int kb  = tid >> 4;            // 0..15
    const int nb  = (tid & 15) * 4;      // 0..60

    float4 pa0, pa1, pbg, pbu;
    const int NT = DDIM / 16;

    auto ldg = [&](int kt) {
        int k0 = kt * 16;
        pa0 = *reinterpret_cast<const float4*>(X + (size_t)(bm + am0)      * DDIM + k0 + akc);
        pa1 = *reinterpret_cast<const float4*>(X + (size_t)(bm + am0 + 64) * DDIM + k0 + akc);
        pbg = *reinterpret_cast<const float4*>(Wg + (size_t)(k0 + kb) * fdim + bn + nb);
        pbu = *reinterpret_cast<const float4*>(Wu + (size_t)(k0 + kb) * fdim + bn + nb);
    };
    auto sts = [&]() {
        As[akc + 0][am0] = pa0.x; As[akc + 1][am0] = pa0.y;
        As[akc + 2][am0] = pa0.z; As[akc + 3][am0] = pa0.w;
        As[akc + 0][am0 + 64] = pa1.x; As[akc + 1][am0 + 64] = pa1.y;
        As[akc + 2][am0 + 64] = pa1.z; As[akc + 3][am0 + 64] = pa1.w;
        *reinterpret_cast<float4*>(&Bgs[kb][nb]) = pbg;
        *reinterpret_cast<float4*>(&Bus[kb][nb]) = pbu;
    };

    ldg(0); sts(); __syncthreads();
    for (int kt = 0; kt < NT; kt++) {
        if (kt + 1 < NT) ldg(kt + 1);
#pragma unroll
        for (int k = 0; k < 16; k++) {
            float a[8];
            *reinterpret_cast<float4*>(a)     = *reinterpret_cast<const float4*>(&As[k][m0]);
            *reinterpret_cast<float4*>(a + 4) = *reinterpret_cast<const float4*>(&As[k][m0 + 4]);
            float4 bg = *reinterpret_cast<const float4*>(&Bgs[k][n0]);
            float4 bu = *reinterpret_cast<const float4*>(&Bus[k][n0]);
#pragma unroll
            for (int i = 0; i < 8; i++) {
                accG[i][0] = fmaf(a[i], bg.x, accG[i][0]);
                accG[i][1] = fmaf(a[i], bg.y, accG[i][1]);
                accG[i][2] = fmaf(a[i], bg.z, accG[i][2]);
                accG[i][3] = fmaf(a[i], bg.w, accG[i][3]);
                accU[i][0] = fmaf(a[i], bu.x, accU[i][0]);
                accU[i][1] = fmaf(a[i], bu.y, accU[i][1]);
                accU[i][2] = fmaf(a[i], bu.z, accU[i][2]);
                accU[i][3] = fmaf(a[i], bu.w, accU[i][3]);
            }
        }
        __syncthreads();
        if (kt + 1 < NT) { sts(); __syncthreads(); }
    }

    const int hcol = hcol_base + e * fdim + bn + n0;
#pragma unroll
    for (int i = 0; i < 8; i++) {
        int t = bm + m0 + i;
        float s = scaled ? g_W[t * NEXP + e] : 1.0f;
        float4 o;
        {
            float g0 = accG[i][0], g1 = accG[i][1], g2 = accG[i][2], g3 = accG[i][3];
            float sg0 = 1.f / (1.f + expf(-g0));
            float sg1 = 1.f / (1.f + expf(-g1));
            float sg2 = 1.f / (1.f + expf(-g2));
            float sg3 = 1.f / (1.f + expf(-g3));
            o.x = g0 * sg0 * accU[i][0] * s;
            o.y = g1 * sg1 * accU[i][1] * s;
            o.z = g2 * sg2 * accU[i][2] * s;
            o.w = g3 * sg3 * accU[i][3] * s;
        }
        *reinterpret_cast<float4*>(g_H + (size_t)t * KDOWN + hcol) = o;
    }
}

// ---------------------------------------------------------------------------
// Down GEMM + combine:  out[T, D] = H[T, 5120] @ [w_down(4096,D); ws_down(1024,D)]
// ---------------------------------------------------------------------------
__global__ __launch_bounds__(256, 2)
void down_kernel(const float* __restrict__ Wd,
                 const float* __restrict__ Wsd,
                 float* __restrict__ out) {
    const int bm = blockIdx.y * 128;
    const int bn = blockIdx.x * 64;
    const int tid = threadIdx.x;

    __shared__ float As[16][132];
    __shared__ float Bs[16][64];

    const int tx = tid & 15, ty = tid >> 4;
    const int m0 = ty * 8, n0 = tx * 4;

    float acc[8][4];
#pragma unroll
    for (int i = 0; i < 8; i++)
#pragma unroll
        for (int j = 0; j < 4; j++) acc[i][j] = 0.f;

    const int am0 = tid >> 2;
    const int akc = (tid & 3) * 4;
    const int kb  = tid >> 4;
    const int nb  = (tid & 15) * 4;

    float4 pa0, pa1, pb;
    const int NT = KDOWN / 16;   // 320

    auto ldg = [&](int kt) {
        int k0 = kt * 16;
        pa0 = *reinterpret_cast<const float4*>(g_H + (size_t)(bm + am0)      * KDOWN + k0 + akc);
        pa1 = *reinterpret_cast<const float4*>(g_H + (size_t)(bm + am0 + 64) * KDOWN + k0 + akc);
        int krow = k0 + kb;
        const float* bptr = (krow < NEXP * FDIM)
                          ? (Wd  + (size_t)krow * DDIM)
                          : (Wsd + (size_t)(krow - NEXP * FDIM) * DDIM);
        pb = *reinterpret_cast<const float4*>(bptr + bn + nb);
    };
    auto sts = [&]() {
        As[akc + 0][am0] = pa0.x; As[akc + 1][am0] = pa0.y;
        As[akc + 2][am0] = pa0.z; As[akc + 3][am0] = pa0.w;
        As[akc + 0][am0 + 64] = pa1.x; As[akc + 1][am0 + 64] = pa1.y;
        As[akc + 2][am0 + 64] = pa1.z; As[akc + 3][am0 + 64] = pa1.w;
        *reinterpret_cast<float4*>(&Bs[kb][nb]) = pb;
    };

    ldg(0); sts(); __syncthreads();
    for (int kt = 0; kt < NT; kt++) {
        if (kt + 1 < NT) ldg(kt + 1);
#pragma unroll
        for (int k = 0; k < 16; k++) {
            float a[8];
            *reinterpret_cast<float4*>(a)     = *reinterpret_cast<const float4*>(&As[k][m0]);
            *reinterpret_cast<float4*>(a + 4) = *reinterpret_cast<const float4*>(&As[k][m0 + 4]);
            float4 b = *reinterpret_cast<const float4*>(&Bs[k][n0]);
#pragma unroll
            for (int i = 0; i < 8; i++) {
                acc[i][0] = fmaf(a[i], b.x, acc[i][0]);
                acc[i][1] = fmaf(a[i], b.y, acc[i][1]);
                acc[i][2] = fmaf(a[i], b.z, acc[i][2]);
                acc[i][3] = fmaf(a[i], b.w, acc[i][3]);
            }
        }
        __syncthreads();
        if (kt + 1 < NT) { sts(); __syncthreads(); }
    }

#pragma unroll
    for (int i = 0; i < 8; i++) {
        int t = bm + m0 + i;
        float4 o;
        o.x = acc[i][0]; o.y = acc[i][1]; o.z = acc[i][2]; o.w = acc[i][3];
        *reinterpret_cast<float4*>(out + (size_t)t * DDIM + bn + n0) = o;
    }
}

// ---------------------------------------------------------------------------
// Launch
// ---------------------------------------------------------------------------
extern "C" void kernel_launch(void* const* d_in, const int* in_sizes, int n_in,
                              void* d_out, int out_size) {
    const float* x   = (const float*)d_in[0];   // hidden_states [2,2048,1024]
    const float* rw  = (const float*)d_in[1];   // router_w [1024,8]
    const float* wg  = (const float*)d_in[2];   // w_gate  [8,1024,512]
    const float* wu  = (const float*)d_in[3];   // w_up    [8,1024,512]
    const float* wd  = (const float*)d_in[4];   // w_down  [8,512,1024]
    const float* wsg = (const float*)d_in[5];   // ws_gate [1024,1024]
    const float* wsu = (const float*)d_in[6];   // ws_up   [1024,1024]
    const float* wsd = (const float*)d_in[7];   // ws_down [1024,1024]
    float* out = (float*)d_out;

    // 1) router (4 warps / block)
    router_kernel<<<T_TOK / 4, 128>>>(x, rw);

    // 2) routed experts gate+up (+silu+scale) -> H[:, 0:4096]
    dim3 g1(FDIM / 64, T_TOK / 128, NEXP);
    gateup_kernel<<<g1, 256>>>(x, wg, wu, FDIM, 0, 1);

    // 3) shared expert gate+up -> H[:, 4096:5120]
    dim3 g2(FSDIM / 64, T_TOK / 128, 1);
    gateup_kernel<<<g2, 256>>>(x, wsg, wsu, FSDIM, NEXP * FDIM, 0);

    // 4) one big down-GEMM does the weighted combine + shared add
    dim3 g3(DDIM / 64, T_TOK / 128, 1);
    down_kernel<<<g3, 256>>>(wd, wsd, out);
}

// round 3
// speedup vs baseline: 2.1948x; 2.1948x over previous
#include <cuda_runtime.h>
#include <cuda_bf16.h>
#include <math.h>
#include <stdint.h>

#define T_TOK 4096
#define DDIM  1024
#define NEXP  8
#define FDIM  512
#define FSDIM 1024
#define KDOWN 5120
#define TOPK  6

#define BK 32
#define MSTRIDE 80                 // smem bytes/row: 64 data + 16 pad (bank-conflict-free)
#define TILEB (128 * MSTRIDE)      // 10240 bytes per 128-row tile

// ---------------- scratch (device globals; no runtime alloc) ---------------
__device__ float g_W[T_TOK * NEXP];
__device__ __nv_bfloat16 g_Xh[T_TOK * DDIM];
__device__ __nv_bfloat16 g_Xl[T_TOK * DDIM];
__device__ __nv_bfloat16 g_Bgh[NEXP * FDIM * DDIM];
__device__ __nv_bfloat16 g_Bgl[NEXP * FDIM * DDIM];
__device__ __nv_bfloat16 g_Buh[NEXP * FDIM * DDIM];
__device__ __nv_bfloat16 g_Bul[NEXP * FDIM * DDIM];
__device__ __nv_bfloat16 g_Bsgh[FSDIM * DDIM];
__device__ __nv_bfloat16 g_Bsgl[FSDIM * DDIM];
__device__ __nv_bfloat16 g_Bsuh[FSDIM * DDIM];
__device__ __nv_bfloat16 g_Bsul[FSDIM * DDIM];
__device__ __nv_bfloat16 g_Bdh[DDIM * KDOWN];    // [n=1024][k=5120] K-major
__device__ __nv_bfloat16 g_Bdl[DDIM * KDOWN];
__device__ __nv_bfloat16 g_Hh[(size_t)T_TOK * KDOWN];
__device__ __nv_bfloat16 g_Hl[(size_t)T_TOK * KDOWN];

// ---------------- helpers ----------------------------------------------------
__device__ __forceinline__ uint32_t smem_u32(const void* p) {
    uint32_t a;
    asm("{ .reg .u64 t; cvta.to.shared.u64 t, %1; cvt.u32.u64 %0, t; }"
        : "=r"(a) : "l"(p));
    return a;
}

#define CP16(dst, src) \
    asm volatile("cp.async.cg.shared.global [%0], [%1], 16;" :: "r"(dst), "l"(src) : "memory")
#define CP_COMMIT() asm volatile("cp.async.commit_group;" ::: "memory")
#define CP_WAIT1()  asm volatile("cp.async.wait_group 1;" ::: "memory")
#define CP_WAIT0()  asm volatile("cp.async.wait_group 0;" ::: "memory")
#define LDS32(v, a) asm volatile("ld.shared.b32 %0, [%1];" : "=r"(v) : "r"(a))

#define MMA16(d, a, b0, b1) \
    asm volatile( \
        "mma.sync.aligned.m16n8k16.row.col.f32.bf16.bf16.f32 " \
        "{%0,%1,%2,%3},{%4,%5,%6,%7},{%8,%9},{%0,%1,%2,%3};" \
        : "+f"((d)[0]), "+f"((d)[1]), "+f"((d)[2]), "+f"((d)[3]) \
        : "r"((a)[0]), "r"((a)[1]), "r"((a)[2]), "r"((a)[3]), "r"(b0), "r"(b1))

__device__ __forceinline__ uint32_t pk_bf2(__nv_bfloat16 a, __nv_bfloat16 b) {
    __nv_bfloat162 t = __halves2bfloat162(a, b);
    return *reinterpret_cast<uint32_t*>(&t);
}
__device__ __forceinline__ void split_bf(float v, __nv_bfloat16& h, __nv_bfloat16& l) {
    h = __float2bfloat16(v);
    l = __float2bfloat16(v - __bfloat162float(h));
}

// ---------------- router -----------------------------------------------------
__global__ void router_kernel(const float* __restrict__ x,
                              const float* __restrict__ rw) {
    int gw = (blockIdx.x * blockDim.x + threadIdx.x) >> 5;
    int lane = threadIdx.x & 31;
    if (gw >= T_TOK) return;
    const float* xr = x + (size_t)gw * DDIM;
    float acc[NEXP];
#pragma unroll
    for (int e = 0; e < NEXP; e++) acc[e] = 0.f;
    for (int d = lane; d < DDIM; d += 32) {
        float xv = xr[d];
        const float4* r4 = reinterpret_cast<const float4*>(rw + (size_t)d * NEXP);
        float4 r0 = r4[0], r1 = r4[1];
        acc[0] = fmaf(xv, r0.x, acc[0]); acc[1] = fmaf(xv, r0.y, acc[1]);
        acc[2] = fmaf(xv, r0.z, acc[2]); acc[3] = fmaf(xv, r0.w, acc[3]);
        acc[4] = fmaf(xv, r1.x, acc[4]); acc[5] = fmaf(xv, r1.y, acc[5]);
        acc[6] = fmaf(xv, r1.z, acc[6]); acc[7] = fmaf(xv, r1.w, acc[7]);
    }
#pragma unroll
    for (int off = 16; off > 0; off >>= 1)
#pragma unroll
        for (int e = 0; e < NEXP; e++)
            acc[e] += __shfl_xor_sync(0xffffffffu, acc[e], off);
    if (lane == 0) {
        float m = acc[0];
#pragma unroll
        for (int e = 1; e < NEXP; e++) m = fmaxf(m, acc[e]);
        float p[NEXP], s = 0.f;
#pragma unroll
        for (int e = 0; e < NEXP; e++) { p[e] = expf(acc[e] - m); s += p[e]; }
        float inv = 1.f / s;
#pragma unroll
        for (int e = 0; e < NEXP; e++) p[e] *= inv;
#pragma unroll
        for (int e = 0; e < NEXP; e++) {
            int rank = 0;
#pragma unroll
            for (int e2 = 0; e2 < NEXP; e2++)
                rank += (p[e2] > p[e] || (p[e2] == p[e] && e2 < e)) ? 1 : 0;
            g_W[gw * NEXP + e] = (rank < TOPK) ? p[e] : 0.f;
        }
    }
}

// ---------------- conversion kernels -----------------------------------------
__global__ void cvt_split(const float* __restrict__ src,
                          __nv_bfloat16* __restrict__ dh,
                          __nv_bfloat16* __restrict__ dl) {
    int i = (blockIdx.x * 256 + threadIdx.x) * 4;
    float4 v = *reinterpret_cast<const float4*>(src + i);
    __nv_bfloat16 h0, l0, h1, l1, h2, l2, h3, l3;
    split_bf(v.x, h0, l0); split_bf(v.y, h1, l1);
    split_bf(v.z, h2, l2); split_bf(v.w, h3, l3);
    uint2 ph, pl;
    ph.x = pk_bf2(h0, h1); ph.y = pk_bf2(h2, h3);
    pl.x = pk_bf2(l0, l1); pl.y = pk_bf2(l2, l3);
    *reinterpret_cast<uint2*>(dh + i) = ph;
    *reinterpret_cast<uint2*>(dl + i) = pl;
}

// dst[n][r] = src[r][n], split into hi/lo bf16.
__global__ void transpose_cvt(const float* __restrict__ src,
                              __nv_bfloat16* __restrict__ dh,
                              __nv_bfloat16* __restrict__ dl,
                              int C, long long src_z, long long dst_z, int dst_rs) {
    __shared__ float t[32][33];
    long long zs = (long long)blockIdx.z * src_z;
    long long zd = (long long)blockIdx.z * dst_z;
    int c0 = blockIdx.x * 32, r0 = blockIdx.y * 32;
    int tx = threadIdx.x, ty = threadIdx.y;
#pragma unroll
    for (int k = 0; k < 32; k += 8)
        t[ty + k][tx] = src[zs + (long long)(r0 + ty + k) * C + c0 + tx];
    __syncthreads();
#pragma unroll
    for (int k = 0; k < 32; k += 8) {
        float v = t[tx][ty + k];
        int n = c0 + ty + k, r = r0 + tx;
        __nv_bfloat16 h, l;
        split_bf(v, h, l);
        dh[zd + (long long)n * dst_rs + r] = h;
        dl[zd + (long long)n * dst_rs + r] = l;
    }
}

// ---------------- fused gate+up HMMA GEMM ------------------------------------
// C tile 128(m) x 128(n) for gate AND up. BK=32 chunks; per chunk the smem holds
// Ah, Al, Bg_h, Bg_l, Bu_h, Bu_l and we issue 3 bf16 passes (AhBh+AhBl+AlBh)
// from the same tiles. 8 warps as 2(m) x 4(n), warp tile 64x32.
#define GU_SBUF (6 * TILEB)       // 61440
#define GU_SMEM (2 * GU_SBUF)     // 122880

__global__ __launch_bounds__(256, 1)
void gu_mma(const __nv_bfloat16* __restrict__ Xh, const __nv_bfloat16* __restrict__ Xl,
            const __nv_bfloat16* __restrict__ Gh, const __nv_bfloat16* __restrict__ Gl,
            const __nv_bfloat16* __restrict__ Uh, const __nv_bfloat16* __restrict__ Ul,
            int fdim, int hbase, int scaled) {
    extern __shared__ __align__(16) char smem[];
    const uint32_t sb = smem_u32(smem);
    const int tid = threadIdx.x;
    const int wid = tid >> 5, lane = tid & 31;
    const int grp = lane >> 2, tI = lane & 3;
    const int wm = (wid >> 2) * 64, wn = (wid & 3) * 32;
    const int bm = blockIdx.y * 128, bn = blockIdx.x * 128;
    const int e = blockIdx.z;
    const size_t beoff = (size_t)e * fdim * DDIM;
    const __nv_bfloat16* Bg_h = Gh + beoff;
    const __nv_bfloat16* Bg_l = Gl + beoff;
    const __nv_bfloat16* Bu_h = Uh + beoff;
    const __nv_bfloat16* Bu_l = Ul + beoff;

    const int lr = tid >> 2, lq = tid & 3;
    const uint32_t ds0 = lr * MSTRIDE + lq * 16;
    const uint32_t ds1 = (lr + 64) * MSTRIDE + lq * 16;
    const size_t gA0 = (size_t)(bm + lr) * DDIM + lq * 8;
    const size_t gA1 = gA0 + (size_t)64 * DDIM;
    const size_t gB0 = (size_t)(bn + lr) * DDIM + lq * 8;
    const size_t gB1 = gB0 + (size_t)64 * DDIM;

    float accG[4][4][4], accU[4][4][4];
#pragma unroll
    for (int i = 0; i < 4; i++)
#pragma unroll
        for (int j = 0; j < 4; j++)
#pragma unroll
            for (int r = 0; r < 4; r++) { accG[i][j][r] = 0.f; accU[i][j][r] = 0.f; }

    const int NC = DDIM / BK;   // 32

    auto issue = [&](int kc, int buf) {
        const int k0 = kc * BK;
        const uint32_t s = sb + buf * GU_SBUF;
        CP16(s + ds0,              Xh   + gA0 + k0);
        CP16(s + ds1,              Xh   + gA1 + k0);
        CP16(s + TILEB + ds0,      Xl   + gA0 + k0);
        CP16(s + TILEB + ds1,      Xl   + gA1 + k0);
        CP16(s + 2 * TILEB + ds0,  Bg_h + gB0 + k0);
        CP16(s + 2 * TILEB + ds1,  Bg_h + gB1 + k0);
        CP16(s + 3 * TILEB + ds0,  Bg_l + gB0 + k0);
        CP16(s + 3 * TILEB + ds1,  Bg_l + gB1 + k0);
        CP16(s + 4 * TILEB + ds0,  Bu_h + gB0 + k0);
        CP16(s + 4 * TILEB + ds1,  Bu_h + gB1 + k0);
        CP16(s + 5 * TILEB + ds0,  Bu_l + gB0 + k0);
        CP16(s + 5 * TILEB + ds1,  Bu_l + gB1 + k0);
        CP_COMMIT();
    };

    issue(0, 0);
    for (int kc = 0; kc < NC; kc++) {
        const int buf = kc & 1;
        if (kc + 1 < NC) { issue(kc + 1, buf ^ 1); CP_WAIT1(); }
        else             { CP_WAIT0(); }
        __syncthreads();
        const uint32_t s = sb + buf * GU_SBUF;
#pragma unroll
        for (int ks = 0; ks < 2; ks++) {
            const uint32_t kb = ks * 32 + tI * 4;
            uint32_t aH[4][4], aL[4][4];
#pragma unroll
            for (int tm = 0; tm < 4; tm++) {
                uint32_t r = s + (wm + tm * 16 + grp) * MSTRIDE + kb;
                LDS32(aH[tm][0], r);
                LDS32(aH[tm][1], r + 8 * MSTRIDE);
                LDS32(aH[tm][2], r + 16);
                LDS32(aH[tm][3], r + 8 * MSTRIDE + 16);
                LDS32(aL[tm][0], r + TILEB);
                LDS32(aL[tm][1], r + TILEB + 8 * MSTRIDE);
                LDS32(aL[tm][2], r + TILEB + 16);
                LDS32(aL[tm][3], r + TILEB + 8 * MSTRIDE + 16);
            }
#pragma unroll
            for (int tn = 0; tn < 4; tn++) {
                const uint32_t r = s + (wn + tn * 8 + grp) * MSTRIDE + kb;
                uint32_t gh0, gh1, gl0, gl1, uh0, uh1, ul0, ul1;
                LDS32(gh0, r + 2 * TILEB); LDS32(gh1, r + 2 * TILEB + 16);
                LDS32(gl0, r + 3 * TILEB); LDS32(gl1, r + 3 * TILEB + 16);
                LDS32(uh0, r + 4 * TILEB); LDS32(uh1, r + 4 * TILEB + 16);
                LDS32(ul0, r + 5 * TILEB); LDS32(ul1, r + 5 * TILEB + 16);
#pragma unroll
                for (int tm = 0; tm < 4; tm++) {
                    MMA16(accG[tm][tn], aH[tm], gh0, gh1);
                    MMA16(accG[tm][tn], aH[tm], gl0, gl1);
                    MMA16(accG[tm][tn], aL[tm], gh0, gh1);
                    MMA16(accU[tm][tn], aH[tm], uh0, uh1);
                    MMA16(accU[tm][tn], aH[tm], ul0, ul1);
                    MMA16(accU[tm][tn], aL[tm], uh0, uh1);
                }
            }
        }
        __syncthreads();
    }

    // epilogue: silu(g)*u*route_weight -> split bf16 -> H
    const int colbase = hbase + e * fdim + bn + wn;
#pragma unroll
    for (int tm = 0; tm < 4; tm++) {
#pragma unroll
        for (int half = 0; half < 2; half++) {
            const int token = bm + wm + tm * 16 + grp + half * 8;
            const float wgt = scaled ? g_W[token * NEXP + e] : 1.0f;
            const size_t rowoff = (size_t)token * KDOWN;
#pragma unroll
            for (int tn = 0; tn < 4; tn++) {
                float gv0 = accG[tm][tn][half * 2 + 0];
                float gv1 = accG[tm][tn][half * 2 + 1];
                float uv0 = accU[tm][tn][half * 2 + 0];
                float uv1 = accU[tm][tn][half * 2 + 1];
                float h0 = gv0 / (1.f + expf(-gv0)) * uv0 * wgt;
                float h1 = gv1 / (1.f + expf(-gv1)) * uv1 * wgt;
                __nv_bfloat16 hh0, hl0, hh1, hl1;
                split_bf(h0, hh0, hl0);
                split_bf(h1, hh1, hl1);
                const int col = colbase + tn * 8 + tI * 2;
                *reinterpret_cast<uint32_t*>(g_Hh + rowoff + col) = pk_bf2(hh0, hh1);
                *reinterpret_cast<uint32_t*>(g_Hl + rowoff + col) = pk_bf2(hl0, hl1);
            }
        }
    }
}

// ---------------- down HMMA GEMM (combine) ------------------------------------
#define DN_SBUF (4 * TILEB)       // 40960
#define DN_SMEM (2 * DN_SBUF)     // 81920

__global__ __launch_bounds__(256, 1)
void dn_mma(float* __restrict__ out) {
    extern __shared__ __align__(16) char smem[];
    const uint32_t sb = smem_u32(smem);
    const int tid = threadIdx.x;
    const int wid = tid >> 5, lane = tid & 31;
    const int grp = lane >> 2, tI = lane & 3;
    const int wm = (wid >> 2) * 64, wn = (wid & 3) * 32;
    const int bm = blockIdx.y * 128, bn = blockIdx.x * 128;

    const int lr = tid >> 2, lq = tid & 3;
    const uint32_t ds0 = lr * MSTRIDE + lq * 16;
    const uint32_t ds1 = (lr + 64) * MSTRIDE + lq * 16;
    const size_t gA0 = (size_t)(bm + lr) * KDOWN + lq * 8;
    const size_t gA1 = gA0 + (size_t)64 * KDOWN;
    const size_t gB0 = (size_t)(bn + lr) * KDOWN + lq * 8;
    const size_t gB1 = gB0 + (size_t)64 * KDOWN;

    float acc[4][4][4];
#pragma unroll
    for (int i = 0; i < 4; i++)
#pragma unroll
        for (int j = 0; j < 4; j++)
#pragma unroll
            for (int r = 0; r < 4; r++) acc[i][j][r] = 0.f;

    const int NC = KDOWN / BK;   // 160

    auto issue = [&](int kc, int buf) {
        const int k0 = kc * BK;
        const uint32_t s = sb + buf * DN_SBUF;
        CP16(s + ds0,              g_Hh  + gA0 + k0);
        CP16(s + ds1,              g_Hh  + gA1 + k0);
        CP16(s + TILEB + ds0,      g_Hl  + gA0 + k0);
        CP16(s + TILEB + ds1,      g_Hl  + gA1 + k0);
        CP16(s + 2 * TILEB + ds0,  g_Bdh + gB0 + k0);
        CP16(s + 2 * TILEB + ds1,  g_Bdh + gB1 + k0);
        CP16(s + 3 * TILEB + ds0,  g_Bdl + gB0 + k0);
        CP16(s + 3 * TILEB + ds1,  g_Bdl + gB1 + k0);
        CP_COMMIT();
    };

    issue(0, 0);
    for (int kc = 0; kc < NC; kc++) {
        const int buf = kc & 1;
        if (kc + 1 < NC) { issue(kc + 1, buf ^ 1); CP_WAIT1(); }
        else             { CP_WAIT0(); }
        __syncthreads();
        const uint32_t s = sb + buf * DN_SBUF;
#pragma unroll
        for (int ks = 0; ks < 2; ks++) {
            const uint32_t kb = ks * 32 + tI * 4;
            uint32_t aH[4][4], aL[4][4];
#pragma unroll
            for (int tm = 0; tm < 4; tm++) {
                uint32_t r = s + (wm + tm * 16 + grp) * MSTRIDE + kb;
                LDS32(aH[tm][0], r);
                LDS32(aH[tm][1], r + 8 * MSTRIDE);
                LDS32(aH[tm][2], r + 16);
                LDS32(aH[tm][3], r + 8 * MSTRIDE + 16);
                LDS32(aL[tm][0], r + TILEB);
                LDS32(aL[tm][1], r + TILEB + 8 * MSTRIDE);
                LDS32(aL[tm][2], r + TILEB + 16);
                LDS32(aL[tm][3], r + TILEB + 8 * MSTRIDE + 16);
            }
#pragma unroll
            for (int tn = 0; tn < 4; tn++) {
                const uint32_t r = s + (wn + tn * 8 + grp) * MSTRIDE + kb;
                uint32_t bh0, bh1, bl0, bl1;
                LDS32(bh0, r + 2 * TILEB); LDS32(bh1, r + 2 * TILEB + 16);
                LDS32(bl0, r + 3 * TILEB); LDS32(bl1, r + 3 * TILEB + 16);
#pragma unroll
                for (int tm = 0; tm < 4; tm++) {
                    MMA16(acc[tm][tn], aH[tm], bh0, bh1);
                    MMA16(acc[tm][tn], aH[tm], bl0, bl1);
                    MMA16(acc[tm][tn], aL[tm], bh0, bh1);
                }
            }
        }
        __syncthreads();
    }

#pragma unroll
    for (int tm = 0; tm < 4; tm++) {
#pragma unroll
        for (int half = 0; half < 2; half++) {
            const int token = bm + wm + tm * 16 + grp + half * 8;
#pragma unroll
            for (int tn = 0; tn < 4; tn++) {
                const int col = bn + wn + tn * 8 + tI * 2;
                float2 v = make_float2(acc[tm][tn][half * 2], acc[tm][tn][half * 2 + 1]);
                *reinterpret_cast<float2*>(out + (size_t)token * DDIM + col) = v;
            }
        }
    }
}

// ---------------- launch ------------------------------------------------------
extern "C" void kernel_launch(void* const* d_in, const int* in_sizes, int n_in,
                              void* d_out, int out_size) {
    const float* x   = (const float*)d_in[0];
    const float* rw  = (const float*)d_in[1];
    const float* wg  = (const float*)d_in[2];
    const float* wu  = (const float*)d_in[3];
    const float* wd  = (const float*)d_in[4];
    const float* wsg = (const float*)d_in[5];
    const float* wsu = (const float*)d_in[6];
    const float* wsd = (const float*)d_in[7];
    float* out = (float*)d_out;

    void *pXh, *pXl, *pBgh, *pBgl, *pBuh, *pBul, *pBsgh, *pBsgl, *pBsuh, *pBsul, *pBdh, *pBdl;
    cudaGetSymbolAddress(&pXh, g_Xh);     cudaGetSymbolAddress(&pXl, g_Xl);
    cudaGetSymbolAddress(&pBgh, g_Bgh);   cudaGetSymbolAddress(&pBgl, g_Bgl);
    cudaGetSymbolAddress(&pBuh, g_Buh);   cudaGetSymbolAddress(&pBul, g_Bul);
    cudaGetSymbolAddress(&pBsgh, g_Bsgh); cudaGetSymbolAddress(&pBsgl, g_Bsgl);
    cudaGetSymbolAddress(&pBsuh, g_Bsuh); cudaGetSymbolAddress(&pBsul, g_Bsul);
    cudaGetSymbolAddress(&pBdh, g_Bdh);   cudaGetSymbolAddress(&pBdl, g_Bdl);

    cudaFuncSetAttribute(gu_mma, cudaFuncAttributeMaxDynamicSharedMemorySize, GU_SMEM);
    cudaFuncSetAttribute(dn_mma, cudaFuncAttributeMaxDynamicSharedMemorySize, DN_SMEM);

    // router weights
    router_kernel<<<T_TOK / 4, 128>>>(x, rw);

    // activations split (hi/lo bf16)
    cvt_split<<<T_TOK * DDIM / 1024, 256>>>(x, (__nv_bfloat16*)pXh, (__nv_bfloat16*)pXl);

    // weight transpose+split into K-major [N][K] hi/lo
    dim3 tb(32, 8);
    transpose_cvt<<<dim3(FDIM / 32, DDIM / 32, NEXP), tb>>>(
        wg, (__nv_bfloat16*)pBgh, (__nv_bfloat16*)pBgl, FDIM,
        (long long)DDIM * FDIM, (long long)FDIM * DDIM, DDIM);
    transpose_cvt<<<dim3(FDIM / 32, DDIM / 32, NEXP), tb>>>(
        wu, (__nv_bfloat16*)pBuh, (__nv_bfloat16*)pBul, FDIM,
        (long long)DDIM * FDIM, (long long)FDIM * DDIM, DDIM);
    transpose_cvt<<<dim3(FSDIM / 32, DDIM / 32, 1), tb>>>(
        wsg, (__nv_bfloat16*)pBsgh, (__nv_bfloat16*)pBsgl, FSDIM, 0, 0, DDIM);
    transpose_cvt<<<dim3(FSDIM / 32, DDIM / 32, 1), tb>>>(
        wsu, (__nv_bfloat16*)pBsuh, (__nv_bfloat16*)pBsul, FSDIM, 0, 0, DDIM);
    // w_down [e][512][1024] -> Bd[n][e*512 + f]
    transpose_cvt<<<dim3(DDIM / 32, FDIM / 32, NEXP), tb>>>(
        wd, (__nv_bfloat16*)pBdh, (__nv_bfloat16*)pBdl, DDIM,
        (long long)FDIM * DDIM, (long long)FDIM, KDOWN);
    // ws_down [1024][1024] -> Bd[n][4096 + f]
    transpose_cvt<<<dim3(DDIM / 32, FSDIM / 32, 1), tb>>>(
        wsd, (__nv_bfloat16*)pBdh + (NEXP * FDIM), (__nv_bfloat16*)pBdl + (NEXP * FDIM),
        DDIM, 0, 0, KDOWN);

    // routed experts: gate+up (+silu, +route weight) -> H[:, 0:4096]
    gu_mma<<<dim3(FDIM / 128, T_TOK / 128, NEXP), 256, GU_SMEM>>>(
        (const __nv_bfloat16*)pXh, (const __nv_bfloat16*)pXl,
        (const __nv_bfloat16*)pBgh, (const __nv_bfloat16*)pBgl,
        (const __nv_bfloat16*)pBuh, (const __nv_bfloat16*)pBul,
        FDIM, 0, 1);
    // shared expert -> H[:, 4096:5120]
    gu_mma<<<dim3(FSDIM / 128, T_TOK / 128, 1), 256, GU_SMEM>>>(
        (const __nv_bfloat16*)pXh, (const __nv_bfloat16*)pXl,
        (const __nv_bfloat16*)pBsgh, (const __nv_bfloat16*)pBsgl,
        (const __nv_bfloat16*)pBsuh, (const __nv_bfloat16*)pBsul,
        FSDIM, NEXP * FDIM, 0);
    // down + weighted combine + shared add, one K=5120 GEMM
    dn_mma<<<dim3(DDIM / 128, T_TOK / 128), 256, DN_SMEM>>>(out);
}

// round 5
// speedup vs baseline: 2.2945x; 1.0454x over previous
#include <cuda_runtime.h>
#include <cuda_bf16.h>
#include <math.h>
#include <stdint.h>

#define T_TOK 4096
#define DDIM  1024
#define NEXP  8
#define FDIM  512
#define FSDIM 1024
#define KDOWN 5120
#define TOPK  6

#define BK 32
#define MSTRIDE 80                 // 64 data + 16 pad: 16B-aligned rows, ldmatrix conflict-free
#define TILEB (128 * MSTRIDE)      // 10240 bytes per 128-row tile

// ---------------- scratch ----------------------------------------------------
__device__ float g_W[T_TOK * NEXP];
__device__ __nv_bfloat16 g_Xh[T_TOK * DDIM];
__device__ __nv_bfloat16 g_Xl[T_TOK * DDIM];
__device__ __nv_bfloat16 g_Bgh[NEXP * FDIM * DDIM];
__device__ __nv_bfloat16 g_Bgl[NEXP * FDIM * DDIM];
__device__ __nv_bfloat16 g_Buh[NEXP * FDIM * DDIM];
__device__ __nv_bfloat16 g_Bul[NEXP * FDIM * DDIM];
__device__ __nv_bfloat16 g_Bsgh[FSDIM * DDIM];
__device__ __nv_bfloat16 g_Bsgl[FSDIM * DDIM];
__device__ __nv_bfloat16 g_Bsuh[FSDIM * DDIM];
__device__ __nv_bfloat16 g_Bsul[FSDIM * DDIM];
__device__ __nv_bfloat16 g_Bdh[DDIM * KDOWN];    // [n=1024][k=5120]
__device__ __nv_bfloat16 g_Bdl[DDIM * KDOWN];
__device__ __nv_bfloat16 g_Hh[(size_t)T_TOK * KDOWN];
__device__ __nv_bfloat16 g_Hl[(size_t)T_TOK * KDOWN];

// ---------------- helpers ----------------------------------------------------
__device__ __forceinline__ uint32_t smem_u32(const void* p) {
    uint32_t a;
    asm("{ .reg .u64 t; cvta.to.shared.u64 t, %1; cvt.u32.u64 %0, t; }"
        : "=r"(a) : "l"(p));
    return a;
}

#define CP16(dst, src) \
    asm volatile("cp.async.cg.shared.global [%0], [%1], 16;" :: "r"(dst), "l"(src) : "memory")
#define CP_COMMIT() asm volatile("cp.async.commit_group;" ::: "memory")
#define CP_WAIT1()  asm volatile("cp.async.wait_group 1;" ::: "memory")
#define CP_WAIT0()  asm volatile("cp.async.wait_group 0;" ::: "memory")

#define LDSM4(r0, r1, r2, r3, a) \
    asm volatile("ldmatrix.sync.aligned.m8n8.x4.shared.b16 {%0,%1,%2,%3}, [%4];" \
        : "=r"(r0), "=r"(r1), "=r"(r2), "=r"(r3) : "r"(a))

#define MMA16(d, a, b0, b1) \
    asm volatile( \
        "mma.sync.aligned.m16n8k16.row.col.f32.bf16.bf16.f32 " \
        "{%0,%1,%2,%3},{%4,%5,%6,%7},{%8,%9},{%0,%1,%2,%3};" \
        : "+f"((d)[0]), "+f"((d)[1]), "+f"((d)[2]), "+f"((d)[3]) \
        : "r"((a)[0]), "r"((a)[1]), "r"((a)[2]), "r"((a)[3]), "r"(b0), "r"(b1))

__device__ __forceinline__ uint32_t pk_bf2(__nv_bfloat16 a, __nv_bfloat16 b) {
    __nv_bfloat162 t = __halves2bfloat162(a, b);
    return *reinterpret_cast<uint32_t*>(&t);
}
__device__ __forceinline__ void split_bf(float v, __nv_bfloat16& h, __nv_bfloat16& l) {
    h = __float2bfloat16(v);
    l = __float2bfloat16(v - __bfloat162float(h));
}

// ---------------- router -----------------------------------------------------
__global__ void router_kernel(const float* __restrict__ x,
                              const float* __restrict__ rw) {
    int gw = (blockIdx.x * blockDim.x + threadIdx.x) >> 5;
    int lane = threadIdx.x & 31;
    if (gw >= T_TOK) return;
    const float* xr = x + (size_t)gw * DDIM;
    float acc[NEXP];
#pragma unroll
    for (int e = 0; e < NEXP; e++) acc[e] = 0.f;
    for (int d = lane; d < DDIM; d += 32) {
        float xv = xr[d];
        const float4* r4 = reinterpret_cast<const float4*>(rw + (size_t)d * NEXP);
        float4 r0 = r4[0], r1 = r4[1];
        acc[0] = fmaf(xv, r0.x, acc[0]); acc[1] = fmaf(xv, r0.y, acc[1]);
        acc[2] = fmaf(xv, r0.z, acc[2]); acc[3] = fmaf(xv, r0.w, acc[3]);
        acc[4] = fmaf(xv, r1.x, acc[4]); acc[5] = fmaf(xv, r1.y, acc[5]);
        acc[6] = fmaf(xv, r1.z, acc[6]); acc[7] = fmaf(xv, r1.w, acc[7]);
    }
#pragma unroll
    for (int off = 16; off > 0; off >>= 1)
#pragma unroll
        for (int e = 0; e < NEXP; e++)
            acc[e] += __shfl_xor_sync(0xffffffffu, acc[e], off);
    if (lane == 0) {
        float m = acc[0];
#pragma unroll
        for (int e = 1; e < NEXP; e++) m = fmaxf(m, acc[e]);
        float p[NEXP], s = 0.f;
#pragma unroll
        for (int e = 0; e < NEXP; e++) { p[e] = expf(acc[e] - m); s += p[e]; }
        float inv = 1.f / s;
#pragma unroll
        for (int e = 0; e < NEXP; e++) p[e] *= inv;
#pragma unroll
        for (int e = 0; e < NEXP; e++) {
            int rank = 0;
#pragma unroll
            for (int e2 = 0; e2 < NEXP; e2++)
                rank += (p[e2] > p[e] || (p[e2] == p[e] && e2 < e)) ? 1 : 0;
            g_W[gw * NEXP + e] = (rank < TOPK) ? p[e] : 0.f;
        }
    }
}

// ---------------- conversions -------------------------------------------------
__global__ void cvt_split(const float* __restrict__ src,
                          __nv_bfloat16* __restrict__ dh,
                          __nv_bfloat16* __restrict__ dl) {
    int i = (blockIdx.x * 256 + threadIdx.x) * 4;
    float4 v = *reinterpret_cast<const float4*>(src + i);
    __nv_bfloat16 h0, l0, h1, l1, h2, l2, h3, l3;
    split_bf(v.x, h0, l0); split_bf(v.y, h1, l1);
    split_bf(v.z, h2, l2); split_bf(v.w, h3, l3);
    uint2 ph, pl;
    ph.x = pk_bf2(h0, h1); ph.y = pk_bf2(h2, h3);
    pl.x = pk_bf2(l0, l1); pl.y = pk_bf2(l2, l3);
    *reinterpret_cast<uint2*>(dh + i) = ph;
    *reinterpret_cast<uint2*>(dl + i) = pl;
}

__device__ __forceinline__ void tpose_body(
    const float* __restrict__ src, __nv_bfloat16* __restrict__ dh,
    __nv_bfloat16* __restrict__ dl, int C, long long zs, long long zd, int rs) {
    __shared__ float t[32][33];
    int c0 = blockIdx.x * 32, r0 = blockIdx.y * 32;
    int tx = threadIdx.x, ty = threadIdx.y;
#pragma unroll
    for (int k = 0; k < 32; k += 8)
        t[ty + k][tx] = src[zs + (long long)(r0 + ty + k) * C + c0 + tx];
    __syncthreads();
#pragma unroll
    for (int k = 0; k < 32; k += 8) {
        float v = t[tx][ty + k];
        int n = c0 + ty + k, r = r0 + tx;
        __nv_bfloat16 h, l;
        split_bf(v, h, l);
        dh[zd + (long long)n * rs + r] = h;
        dl[zd + (long long)n * rs + r] = l;
    }
}

// z 0..7: w_gate expert z ; z 8..15: w_up expert z-8.  grid(16, 32, 16)
__global__ void prepA(const float* __restrict__ wg, const float* __restrict__ wu,
                      __nv_bfloat16* gh, __nv_bfloat16* gl,
                      __nv_bfloat16* uh, __nv_bfloat16* ul) {
    int z = blockIdx.z;
    if (z < 8)
        tpose_body(wg, gh, gl, FDIM, (long long)z * DDIM * FDIM, (long long)z * FDIM * DDIM, DDIM);
    else
        tpose_body(wu, uh, ul, FDIM, (long long)(z - 8) * DDIM * FDIM, (long long)(z - 8) * FDIM * DDIM, DDIM);
}

// z 0: ws_gate  z 1: ws_up  z 2..9: w_down expert z-2 (y<16)  z 10: ws_down. grid(32, 32, 11)
__global__ void prepB(const float* __restrict__ wsg, const float* __restrict__ wsu,
                      const float* __restrict__ wd,  const float* __restrict__ wsd,
                      __nv_bfloat16* sgh, __nv_bfloat16* sgl,
                      __nv_bfloat16* suh, __nv_bfloat16* sul,
                      __nv_bfloat16* bdh, __nv_bfloat16* bdl) {
    int z = blockIdx.z;
    if (z == 0)      tpose_body(wsg, sgh, sgl, FSDIM, 0, 0, DDIM);
    else if (z == 1) tpose_body(wsu, suh, sul, FSDIM, 0, 0, DDIM);
    else if (z <= 9) {
        if (blockIdx.y >= 16) return;   // w_down rows = FDIM = 512
        int e = z - 2;
        tpose_body(wd, bdh, bdl, DDIM, (long long)e * FDIM * DDIM, (long long)e * FDIM, KDOWN);
    } else
        tpose_body(wsd, bdh, bdl, DDIM, 0, (long long)NEXP * FDIM, KDOWN);
}

// ---------------- fused gate+up HMMA GEMM ------------------------------------
#define GU_SBUF (6 * TILEB)       // 61440
#define GU_SMEM (2 * GU_SBUF)     // 122880

__global__ __launch_bounds__(256, 1)
void gu_mma(const __nv_bfloat16* __restrict__ Xh, const __nv_bfloat16* __restrict__ Xl,
            const __nv_bfloat16* __restrict__ Gh, const __nv_bfloat16* __restrict__ Gl,
            const __nv_bfloat16* __restrict__ Uh, const __nv_bfloat16* __restrict__ Ul,
            int fdim, int hbase, int scaled) {
    extern __shared__ __align__(16) char smem[];
    const uint32_t sb = smem_u32(smem);
    const int tid = threadIdx.x;
    const int wid = tid >> 5, lane = tid & 31;
    const int grp = lane >> 2, tI = lane & 3;
    const int wm = (wid >> 2) * 64, wn = (wid & 3) * 32;
    const int bm = blockIdx.y * 128, bn = blockIdx.x * 128;
    const int e = blockIdx.z;
    const size_t beoff = (size_t)e * fdim * DDIM;
    const __nv_bfloat16* Bg_h = Gh + beoff;
    const __nv_bfloat16* Bg_l = Gl + beoff;
    const __nv_bfloat16* Bu_h = Uh + beoff;
    const __nv_bfloat16* Bu_l = Ul + beoff;

    // cp.async staging slots
    const int lr = tid >> 2, lq = tid & 3;
    const uint32_t ds0 = lr * MSTRIDE + lq * 16;
    const uint32_t ds1 = (lr + 64) * MSTRIDE + lq * 16;
    const size_t gA0 = (size_t)(bm + lr) * DDIM + lq * 8;
    const size_t gA1 = gA0 + (size_t)64 * DDIM;
    const size_t gB0 = (size_t)(bn + lr) * DDIM + lq * 8;
    const size_t gB1 = gB0 + (size_t)64 * DDIM;

    // ldmatrix per-lane offsets
    const uint32_t aOff = (lane & 15) * MSTRIDE + (lane >> 4) * 16;
    const uint32_t bOff = (lane & 7) * MSTRIDE + ((lane >> 3) & 1) * 16 + (lane >> 4) * TILEB;

    float accG[4][4][4], accU[4][4][4];
#pragma unroll
    for (int i = 0; i < 4; i++)
#pragma unroll
        for (int j = 0; j < 4; j++)
#pragma unroll
            for (int r = 0; r < 4; r++) { accG[i][j][r] = 0.f; accU[i][j][r] = 0.f; }

    const int NC = DDIM / BK;   // 32

    auto issue = [&](int kc, int buf) {
        const int k0 = kc * BK;
        const uint32_t s = sb + buf * GU_SBUF;
        CP16(s + ds0,              Xh   + gA0 + k0);
        CP16(s + ds1,              Xh   + gA1 + k0);
        CP16(s + TILEB + ds0,      Xl   + gA0 + k0);
        CP16(s + TILEB + ds1,      Xl   + gA1 + k0);
        CP16(s + 2 * TILEB + ds0,  Bg_h + gB0 + k0);
        CP16(s + 2 * TILEB + ds1,  Bg_h + gB1 + k0);
        CP16(s + 3 * TILEB + ds0,  Bg_l + gB0 + k0);
        CP16(s + 3 * TILEB + ds1,  Bg_l + gB1 + k0);
        CP16(s + 4 * TILEB + ds0,  Bu_h + gB0 + k0);
        CP16(s + 4 * TILEB + ds1,  Bu_h + gB1 + k0);
        CP16(s + 5 * TILEB + ds0,  Bu_l + gB0 + k0);
        CP16(s + 5 * TILEB + ds1,  Bu_l + gB1 + k0);
        CP_COMMIT();
    };

    issue(0, 0);
    for (int kc = 0; kc < NC; kc++) {
        const int buf = kc & 1;
        if (kc + 1 < NC) { issue(kc + 1, buf ^ 1); CP_WAIT1(); }
        else             { CP_WAIT0(); }
        __syncthreads();
        const uint32_t s = sb + buf * GU_SBUF;
#pragma unroll
        for (int ks = 0; ks < 2; ks++) {
            uint32_t aH[4][4], aL[4][4];
            const uint32_t aBase = s + wm * MSTRIDE + aOff + ks * 32;
#pragma unroll
            for (int tm = 0; tm < 4; tm++) {
                const uint32_t ad = aBase + tm * 16 * MSTRIDE;
                LDSM4(aH[tm][0], aH[tm][1], aH[tm][2], aH[tm][3], ad);
                LDSM4(aL[tm][0], aL[tm][1], aL[tm][2], aL[tm][3], ad + TILEB);
            }
            const uint32_t bBase = s + 2 * TILEB + wn * MSTRIDE + bOff + ks * 32;
#pragma unroll
            for (int tn = 0; tn < 4; tn++) {
                const uint32_t bd = bBase + tn * 8 * MSTRIDE;
                uint32_t g[4], u[4];
                LDSM4(g[0], g[1], g[2], g[3], bd);              // gh0 gh1 gl0 gl1
                LDSM4(u[0], u[1], u[2], u[3], bd + 2 * TILEB);  // uh0 uh1 ul0 ul1
#pragma unroll
                for (int tm = 0; tm < 4; tm++) {
                    MMA16(accG[tm][tn], aH[tm], g[0], g[1]);
                    MMA16(accG[tm][tn], aH[tm], g[2], g[3]);
                    MMA16(accG[tm][tn], aL[tm], g[0], g[1]);
                    MMA16(accU[tm][tn], aH[tm], u[0], u[1]);
                    MMA16(accU[tm][tn], aH[tm], u[2], u[3]);
                    MMA16(accU[tm][tn], aL[tm], u[0], u[1]);
                }
            }
        }
        __syncthreads();
    }

    // epilogue: silu(g)*u*route_weight -> split bf16 -> H
    const int colbase = hbase + e * fdim + bn + wn;
#pragma unroll
    for (int tm = 0; tm < 4; tm++) {
#pragma unroll
        for (int half = 0; half < 2; half++) {
            const int token = bm + wm + tm * 16 + grp + half * 8;
            const float wgt = scaled ? g_W[token * NEXP + e] : 1.0f;
            const size_t rowoff = (size_t)token * KDOWN;
#pragma unroll
            for (int tn = 0; tn < 4; tn++) {
                float gv0 = accG[tm][tn][half * 2 + 0];
                float gv1 = accG[tm][tn][half * 2 + 1];
                float uv0 = accU[tm][tn][half * 2 + 0];
                float uv1 = accU[tm][tn][half * 2 + 1];
                float h0 = gv0 / (1.f + expf(-gv0)) * uv0 * wgt;
                float h1 = gv1 / (1.f + expf(-gv1)) * uv1 * wgt;
                __nv_bfloat16 hh0, hl0, hh1, hl1;
                split_bf(h0, hh0, hl0);
                split_bf(h1, hh1, hl1);
                const int col = colbase + tn * 8 + tI * 2;
                *reinterpret_cast<uint32_t*>(g_Hh + rowoff + col) = pk_bf2(hh0, hh1);
                *reinterpret_cast<uint32_t*>(g_Hl + rowoff + col) = pk_bf2(hl0, hl1);
            }
        }
    }
}

// ---------------- down HMMA GEMM (combine) -------------------------------------
#define DN_SBUF (4 * TILEB)       // 40960
#define DN_SMEM (2 * DN_SBUF)     // 81920

__global__ __launch_bounds__(256, 2)
void dn_mma(float* __restrict__ out) {
    extern __shared__ __align__(16) char smem[];
    const uint32_t sb = smem_u32(smem);
    const int tid = threadIdx.x;
    const int wid = tid >> 5, lane = tid & 31;
    const int grp = lane >> 2, tI = lane & 3;
    const int wm = (wid >> 2) * 64, wn = (wid & 3) * 32;
    const int bm = blockIdx.y * 128, bn = blockIdx.x * 128;

    const int lr = tid >> 2, lq = tid & 3;
    const uint32_t ds0 = lr * MSTRIDE + lq * 16;
    const uint32_t ds1 = (lr + 64) * MSTRIDE + lq * 16;
    const size_t gA0 = (size_t)(bm + lr) * KDOWN + lq * 8;
    const size_t gA1 = gA0 + (size_t)64 * KDOWN;
    const size_t gB0 = (size_t)(bn + lr) * KDOWN + lq * 8;
    const size_t gB1 = gB0 + (size_t)64 * KDOWN;

    const uint32_t aOff = (lane & 15) * MSTRIDE + (lane >> 4) * 16;
    const uint32_t bOff = (lane & 7) * MSTRIDE + ((lane >> 3) & 1) * 16 + (lane >> 4) * TILEB;

    float acc[4][4][4];
#pragma unroll
    for (int i = 0; i < 4; i++)
#pragma unroll
        for (int j = 0; j < 4; j++)
#pragma unroll
            for (int r = 0; r < 4; r++) acc[i][j][r] = 0.f;

    const int NC = KDOWN / BK;   // 160

    auto issue = [&](int kc, int buf) {
        const int k0 = kc * BK;
        const uint32_t s = sb + buf * DN_SBUF;
        CP16(s + ds0,              g_Hh  + gA0 + k0);
        CP16(s + ds1,              g_Hh  + gA1 + k0);
        CP16(s + TILEB + ds0,      g_Hl  + gA0 + k0);
        CP16(s + TILEB + ds1,      g_Hl  + gA1 + k0);
        CP16(s + 2 * TILEB + ds0,  g_Bdh + gB0 + k0);
        CP16(s + 2 * TILEB + ds1,  g_Bdh + gB1 + k0);
        CP16(s + 3 * TILEB + ds0,  g_Bdl + gB0 + k0);
        CP16(s + 3 * TILEB + ds1,  g_Bdl + gB1 + k0);
        CP_COMMIT();
    };

    issue(0, 0);
    for (int kc = 0; kc < NC; kc++) {
        const int buf = kc & 1;
        if (kc + 1 < NC) { issue(kc + 1, buf ^ 1); CP_WAIT1(); }
        else             { CP_WAIT0(); }
        __syncthreads();
        const uint32_t s = sb + buf * DN_SBUF;
#pragma unroll
        for (int ks = 0; ks < 2; ks++) {
            uint32_t aH[4][4], aL[4][4];
            const uint32_t aBase = s + wm * MSTRIDE + aOff + ks * 32;
#pragma unroll
            for (int tm = 0; tm < 4; tm++) {
                const uint32_t ad = aBase + tm * 16 * MSTRIDE;
                LDSM4(aH[tm][0], aH[tm][1], aH[tm][2], aH[tm][3], ad);
                LDSM4(aL[tm][0], aL[tm][1], aL[tm][2], aL[tm][3], ad + TILEB);
            }
            const uint32_t bBase = s + 2 * TILEB + wn * MSTRIDE + bOff + ks * 32;
#pragma unroll
            for (int tn = 0; tn < 4; tn++) {
                uint32_t b[4];
                LDSM4(b[0], b[1], b[2], b[3], bBase + tn * 8 * MSTRIDE);  // bh0 bh1 bl0 bl1
#pragma unroll
                for (int tm = 0; tm < 4; tm++) {
                    MMA16(acc[tm][tn], aH[tm], b[0], b[1]);
                    MMA16(acc[tm][tn], aH[tm], b[2], b[3]);
                    MMA16(acc[tm][tn], aL[tm], b[0], b[1]);
                }
            }
        }
        __syncthreads();
    }

#pragma unroll
    for (int tm = 0; tm < 4; tm++) {
#pragma unroll
        for (int half = 0; half < 2; half++) {
            const int token = bm + wm + tm * 16 + grp + half * 8;
#pragma unroll
            for (int tn = 0; tn < 4; tn++) {
                const int col = bn + wn + tn * 8 + tI * 2;
                float2 v = make_float2(acc[tm][tn][half * 2], acc[tm][tn][half * 2 + 1]);
                *reinterpret_cast<float2*>(out + (size_t)token * DDIM + col) = v;
            }
        }
    }
}

// ---------------- launch --------------------------------------------------------
extern "C" void kernel_launch(void* const* d_in, const int* in_sizes, int n_in,
                              void* d_out, int out_size) {
    const float* x   = (const float*)d_in[0];
    const float* rw  = (const float*)d_in[1];
    const float* wg  = (const float*)d_in[2];
    const float* wu  = (const float*)d_in[3];
    const float* wd  = (const float*)d_in[4];
    const float* wsg = (const float*)d_in[5];
    const float* wsu = (const float*)d_in[6];
    const float* wsd = (const float*)d_in[7];
    float* out = (float*)d_out;

    void *pXh, *pXl, *pBgh, *pBgl, *pBuh, *pBul, *pBsgh, *pBsgl, *pBsuh, *pBsul, *pBdh, *pBdl;
    cudaGetSymbolAddress(&pXh, g_Xh);     cudaGetSymbolAddress(&pXl, g_Xl);
    cudaGetSymbolAddress(&pBgh, g_Bgh);   cudaGetSymbolAddress(&pBgl, g_Bgl);
    cudaGetSymbolAddress(&pBuh, g_Buh);   cudaGetSymbolAddress(&pBul, g_Bul);
    cudaGetSymbolAddress(&pBsgh, g_Bsgh); cudaGetSymbolAddress(&pBsgl, g_Bsgl);
    cudaGetSymbolAddress(&pBsuh, g_Bsuh); cudaGetSymbolAddress(&pBsul, g_Bsul);
    cudaGetSymbolAddress(&pBdh, g_Bdh);   cudaGetSymbolAddress(&pBdl, g_Bdl);

    cudaFuncSetAttribute(gu_mma, cudaFuncAttributeMaxDynamicSharedMemorySize, GU_SMEM);
    cudaFuncSetAttribute(dn_mma, cudaFuncAttributeMaxDynamicSharedMemorySize, DN_SMEM);

    // 1: router
    router_kernel<<<T_TOK / 4, 128>>>(x, rw);
    // 2: activation split
    cvt_split<<<T_TOK * DDIM / 1024, 256>>>(x, (__nv_bfloat16*)pXh, (__nv_bfloat16*)pXl);
    // 3: w_gate + w_up transpose/split
    dim3 tb(32, 8);
    prepA<<<dim3(16, 32, 16), tb>>>(wg, wu,
        (__nv_bfloat16*)pBgh, (__nv_bfloat16*)pBgl,
        (__nv_bfloat16*)pBuh, (__nv_bfloat16*)pBul);
    // 4: shared weights + down weights transpose/split
    prepB<<<dim3(32, 32, 11), tb>>>(wsg, wsu, wd, wsd,
        (__nv_bfloat16*)pBsgh, (__nv_bfloat16*)pBsgl,
        (__nv_bfloat16*)pBsuh, (__nv_bfloat16*)pBsul,
        (__nv_bfloat16*)pBdh,  (__nv_bfloat16*)pBdl);
    // 5: shared expert gate+up -> H[:, 4096:5120]
    gu_mma<<<dim3(FSDIM / 128, T_TOK / 128, 1), 256, GU_SMEM>>>(
        (const __nv_bfloat16*)pXh, (const __nv_bfloat16*)pXl,
        (const __nv_bfloat16*)pBsgh, (const __nv_bfloat16*)pBsgl,
        (const __nv_bfloat16*)pBsuh, (const __nv_bfloat16*)pBsul,
        FSDIM, NEXP * FDIM, 0);
    // 6: routed experts gate+up -> H[:, 0:4096]   (ncu -s 5 -c 1 lands here)
    gu_mma<<<dim3(FDIM / 128, T_TOK / 128, NEXP), 256, GU_SMEM>>>(
        (const __nv_bfloat16*)pXh, (const __nv_bfloat16*)pXl,
        (const __nv_bfloat16*)pBgh, (const __nv_bfloat16*)pBgl,
        (const __nv_bfloat16*)pBuh, (const __nv_bfloat16*)pBul,
        FDIM, 0, 1);
    // 7: down + weighted combine + shared add
    dn_mma<<<dim3(DDIM / 128, T_TOK / 128), 256, DN_SMEM>>>(out);
}

// round 6
// speedup vs baseline: 2.3631x; 1.0299x over previous
#include <cuda_runtime.h>
#include <cuda_bf16.h>
#include <math.h>
#include <stdint.h>

#define T_TOK 4096
#define DDIM  1024
#define NEXP  8
#define FDIM  512
#define FSDIM 1024
#define KDOWN 5120
#define TOPK  6

#define BK 32
#define MSTRIDE 80                 // 64 data + 16 pad: 16B-aligned rows, ldmatrix conflict-free
#define TILEB (128 * MSTRIDE)      // 10240 bytes per 128-row tile
#define IDXSTR 4224                // per-expert index list stride (4096 + pad)

// ---------------- scratch ----------------------------------------------------
__device__ float g_W[T_TOK * NEXP];
__device__ int   g_idx[NEXP * IDXSTR];
__device__ int   g_idxI[T_TOK];
__device__ int   g_cnt[NEXP];
__device__ int   g_cntp[NEXP];
__device__ __nv_bfloat16 g_Xh[T_TOK * DDIM];
__device__ __nv_bfloat16 g_Xl[T_TOK * DDIM];
__device__ __nv_bfloat16 g_Bgh[NEXP * FDIM * DDIM];
__device__ __nv_bfloat16 g_Bgl[NEXP * FDIM * DDIM];
__device__ __nv_bfloat16 g_Buh[NEXP * FDIM * DDIM];
__device__ __nv_bfloat16 g_Bul[NEXP * FDIM * DDIM];
__device__ __nv_bfloat16 g_Bsgh[FSDIM * DDIM];
__device__ __nv_bfloat16 g_Bsgl[FSDIM * DDIM];
__device__ __nv_bfloat16 g_Bsuh[FSDIM * DDIM];
__device__ __nv_bfloat16 g_Bsul[FSDIM * DDIM];
__device__ __nv_bfloat16 g_Bdh[DDIM * KDOWN];    // [n=1024][k=5120]
__device__ __nv_bfloat16 g_Bdl[DDIM * KDOWN];
__device__ __nv_bfloat16 g_Hh[(size_t)T_TOK * KDOWN];
__device__ __nv_bfloat16 g_Hl[(size_t)T_TOK * KDOWN];

// ---------------- helpers ----------------------------------------------------
__device__ __forceinline__ uint32_t smem_u32(const void* p) {
    uint32_t a;
    asm("{ .reg .u64 t; cvta.to.shared.u64 t, %1; cvt.u32.u64 %0, t; }"
        : "=r"(a) : "l"(p));
    return a;
}

#define CP16(dst, src) \
    asm volatile("cp.async.cg.shared.global [%0], [%1], 16;" :: "r"(dst), "l"(src) : "memory")
#define CP_COMMIT() asm volatile("cp.async.commit_group;" ::: "memory")
#define CP_WAIT1()  asm volatile("cp.async.wait_group 1;" ::: "memory")
#define CP_WAIT0()  asm volatile("cp.async.wait_group 0;" ::: "memory")

#define LDSM4(r0, r1, r2, r3, a) \
    asm volatile("ldmatrix.sync.aligned.m8n8.x4.shared.b16 {%0,%1,%2,%3}, [%4];" \
        : "=r"(r0), "=r"(r1), "=r"(r2), "=r"(r3) : "r"(a))

#define MMA16(d, a, b0, b1) \
    asm volatile( \
        "mma.sync.aligned.m16n8k16.row.col.f32.bf16.bf16.f32 " \
        "{%0,%1,%2,%3},{%4,%5,%6,%7},{%8,%9},{%0,%1,%2,%3};" \
        : "+f"((d)[0]), "+f"((d)[1]), "+f"((d)[2]), "+f"((d)[3]) \
        : "r"((a)[0]), "r"((a)[1]), "r"((a)[2]), "r"((a)[3]), "r"(b0), "r"(b1))

__device__ __forceinline__ uint32_t pk_bf2(__nv_bfloat16 a, __nv_bfloat16 b) {
    __nv_bfloat162 t = __halves2bfloat162(a, b);
    return *reinterpret_cast<uint32_t*>(&t);
}
__device__ __forceinline__ void split_bf(float v, __nv_bfloat16& h, __nv_bfloat16& l) {
    h = __float2bfloat16(v);
    l = __float2bfloat16(v - __bfloat162float(h));
}

// ---------------- init: zero expert counters, identity index list -------------
__global__ void init_lists() {
    int t = blockIdx.x * 256 + threadIdx.x;
    if (t < T_TOK) g_idxI[t] = t;
    if (t < NEXP)  g_cnt[t] = 0;
}

// ---------------- router + per-expert token list build ------------------------
__global__ void router_kernel(const float* __restrict__ x,
                              const float* __restrict__ rw) {
    int gw = (blockIdx.x * blockDim.x + threadIdx.x) >> 5;
    int lane = threadIdx.x & 31;
    if (gw >= T_TOK) return;
    const float* xr = x + (size_t)gw * DDIM;
    float acc[NEXP];
#pragma unroll
    for (int e = 0; e < NEXP; e++) acc[e] = 0.f;
    for (int d = lane; d < DDIM; d += 32) {
        float xv = xr[d];
        const float4* r4 = reinterpret_cast<const float4*>(rw + (size_t)d * NEXP);
        float4 r0 = r4[0], r1 = r4[1];
        acc[0] = fmaf(xv, r0.x, acc[0]); acc[1] = fmaf(xv, r0.y, acc[1]);
        acc[2] = fmaf(xv, r0.z, acc[2]); acc[3] = fmaf(xv, r0.w, acc[3]);
        acc[4] = fmaf(xv, r1.x, acc[4]); acc[5] = fmaf(xv, r1.y, acc[5]);
        acc[6] = fmaf(xv, r1.z, acc[6]); acc[7] = fmaf(xv, r1.w, acc[7]);
    }
#pragma unroll
    for (int off = 16; off > 0; off >>= 1)
#pragma unroll
        for (int e = 0; e < NEXP; e++)
            acc[e] += __shfl_xor_sync(0xffffffffu, acc[e], off);
    if (lane == 0) {
        float m = acc[0];
#pragma unroll
        for (int e = 1; e < NEXP; e++) m = fmaxf(m, acc[e]);
        float p[NEXP], s = 0.f;
#pragma unroll
        for (int e = 0; e < NEXP; e++) { p[e] = expf(acc[e] - m); s += p[e]; }
        float inv = 1.f / s;
#pragma unroll
        for (int e = 0; e < NEXP; e++) p[e] *= inv;
#pragma unroll
        for (int e = 0; e < NEXP; e++) {
            int rank = 0;
#pragma unroll
            for (int e2 = 0; e2 < NEXP; e2++)
                rank += (p[e2] > p[e] || (p[e2] == p[e] && e2 < e)) ? 1 : 0;
            bool sel = (rank < TOPK);
            g_W[gw * NEXP + e] = sel ? p[e] : 0.f;
            if (sel) {
                int pos = atomicAdd(&g_cnt[e], 1);
                g_idx[e * IDXSTR + pos] = gw;
            }
        }
    }
}

// ---------------- pad index lists to multiple of 128 ---------------------------
__global__ void pad_idx() {
    int e = blockIdx.x;
    int cnt = g_cnt[e];
    int cntp = (cnt + 127) & ~127;
    if (threadIdx.x == 0) g_cntp[e] = cntp;
    if (cnt == 0) return;
    int last = g_idx[e * IDXSTR + cnt - 1];
    for (int i = cnt + threadIdx.x; i < cntp; i += 128)
        g_idx[e * IDXSTR + i] = last;
}

// ---------------- zero H (unselected (t,e) slots must read as 0) ---------------
__global__ void zeroH() {
    size_t i = ((size_t)blockIdx.x * 256 + threadIdx.x) * 8;
    uint4 z = make_uint4(0, 0, 0, 0);
    *reinterpret_cast<uint4*>(g_Hh + i) = z;
    *reinterpret_cast<uint4*>(g_Hl + i) = z;
}

// ---------------- conversions --------------------------------------------------
__global__ void cvt_split(const float* __restrict__ src,
                          __nv_bfloat16* __restrict__ dh,
                          __nv_bfloat16* __restrict__ dl) {
    int i = (blockIdx.x * 256 + threadIdx.x) * 4;
    float4 v = *reinterpret_cast<const float4*>(src + i);
    __nv_bfloat16 h0, l0, h1, l1, h2, l2, h3, l3;
    split_bf(v.x, h0, l0); split_bf(v.y, h1, l1);
    split_bf(v.z, h2, l2); split_bf(v.w, h3, l3);
    uint2 ph, pl;
    ph.x = pk_bf2(h0, h1); ph.y = pk_bf2(h2, h3);
    pl.x = pk_bf2(l0, l1); pl.y = pk_bf2(l2, l3);
    *reinterpret_cast<uint2*>(dh + i) = ph;
    *reinterpret_cast<uint2*>(dl + i) = pl;
}

__device__ __forceinline__ void tpose_body(
    const float* __restrict__ src, __nv_bfloat16* __restrict__ dh,
    __nv_bfloat16* __restrict__ dl, int C, long long zs, long long zd, int rs) {
    __shared__ float t[32][33];
    int c0 = blockIdx.x * 32, r0 = blockIdx.y * 32;
    int tx = threadIdx.x, ty = threadIdx.y;
#pragma unroll
    for (int k = 0; k < 32; k += 8)
        t[ty + k][tx] = src[zs + (long long)(r0 + ty + k) * C + c0 + tx];
    __syncthreads();
#pragma unroll
    for (int k = 0; k < 32; k += 8) {
        float v = t[tx][ty + k];
        int n = c0 + ty + k, r = r0 + tx;
        __nv_bfloat16 h, l;
        split_bf(v, h, l);
        dh[zd + (long long)n * rs + r] = h;
        dl[zd + (long long)n * rs + r] = l;
    }
}

__global__ void prepA(const float* __restrict__ wg, const float* __restrict__ wu,
                      __nv_bfloat16* gh, __nv_bfloat16* gl,
                      __nv_bfloat16* uh, __nv_bfloat16* ul) {
    int z = blockIdx.z;
    if (z < 8)
        tpose_body(wg, gh, gl, FDIM, (long long)z * DDIM * FDIM, (long long)z * FDIM * DDIM, DDIM);
    else
        tpose_body(wu, uh, ul, FDIM, (long long)(z - 8) * DDIM * FDIM, (long long)(z - 8) * FDIM * DDIM, DDIM);
}

__global__ void prepB(const float* __restrict__ wsg, const float* __restrict__ wsu,
                      const float* __restrict__ wd,  const float* __restrict__ wsd,
                      __nv_bfloat16* sgh, __nv_bfloat16* sgl,
                      __nv_bfloat16* suh, __nv_bfloat16* sul,
                      __nv_bfloat16* bdh, __nv_bfloat16* bdl) {
    int z = blockIdx.z;
    if (z == 0)      tpose_body(wsg, sgh, sgl, FSDIM, 0, 0, DDIM);
    else if (z == 1) tpose_body(wsu, suh, sul, FSDIM, 0, 0, DDIM);
    else if (z <= 9) {
        if (blockIdx.y >= 16) return;   // w_down rows = FDIM = 512
        int e = z - 2;
        tpose_body(wd, bdh, bdl, DDIM, (long long)e * FDIM * DDIM, (long long)e * FDIM, KDOWN);
    } else
        tpose_body(wsd, bdh, bdl, DDIM, 0, (long long)NEXP * FDIM, KDOWN);
}

// ---------------- fused gate+up HMMA GEMM (gathered tokens) --------------------
#define GU_SBUF (6 * TILEB)       // 61440
#define GU_SMEM (2 * GU_SBUF)     // 122880

__global__ __launch_bounds__(256, 1)
void gu_mma(const __nv_bfloat16* __restrict__ Xh, const __nv_bfloat16* __restrict__ Xl,
            const __nv_bfloat16* __restrict__ Gh, const __nv_bfloat16* __restrict__ Gl,
            const __nv_bfloat16* __restrict__ Uh, const __nv_bfloat16* __restrict__ Ul,
            const int* __restrict__ tix_base, int tix_stride,
            const int* __restrict__ cntp,
            int fdim, int hbase, int scaled) {
    extern __shared__ __align__(16) char smem[];
    const uint32_t sb = smem_u32(smem);
    const int tid = threadIdx.x;
    const int wid = tid >> 5, lane = tid & 31;
    const int grp = lane >> 2, tI = lane & 3;
    const int wm = (wid >> 2) * 64, wn = (wid & 3) * 32;
    const int bm = blockIdx.y * 128, bn = blockIdx.x * 128;
    const int e = blockIdx.z;
    if (cntp && bm >= cntp[e]) return;
    const int* tix = tix_base + (size_t)e * tix_stride;
    const size_t beoff = (size_t)e * fdim * DDIM;
    const __nv_bfloat16* Bg_h = Gh + beoff;
    const __nv_bfloat16* Bg_l = Gl + beoff;
    const __nv_bfloat16* Bu_h = Uh + beoff;
    const __nv_bfloat16* Bu_l = Ul + beoff;

    // cp.async staging slots (A rows gathered through token index list)
    const int lr = tid >> 2, lq = tid & 3;
    const uint32_t ds0 = lr * MSTRIDE + lq * 16;
    const uint32_t ds1 = (lr + 64) * MSTRIDE + lq * 16;
    const int tokA0 = tix[bm + lr];
    const int tokA1 = tix[bm + lr + 64];
    const size_t gA0 = (size_t)tokA0 * DDIM + lq * 8;
    const size_t gA1 = (size_t)tokA1 * DDIM + lq * 8;
    const size_t gB0 = (size_t)(bn + lr) * DDIM + lq * 8;
    const size_t gB1 = gB0 + (size_t)64 * DDIM;

    // ldmatrix per-lane offsets
    const uint32_t aOff = (lane & 15) * MSTRIDE + (lane >> 4) * 16;
    const uint32_t bOff = (lane & 7) * MSTRIDE + ((lane >> 3) & 1) * 16 + (lane >> 4) * TILEB;

    float accG[4][4][4], accU[4][4][4];
#pragma unroll
    for (int i = 0; i < 4; i++)
#pragma unroll
        for (int j = 0; j < 4; j++)
#pragma unroll
            for (int r = 0; r < 4; r++) { accG[i][j][r] = 0.f; accU[i][j][r] = 0.f; }

    const int NC = DDIM / BK;   // 32

    auto issue = [&](int kc, int buf) {
        const int k0 = kc * BK;
        const uint32_t s = sb + buf * GU_SBUF;
        CP16(s + ds0,              Xh   + gA0 + k0);
        CP16(s + ds1,              Xh   + gA1 + k0);
        CP16(s + TILEB + ds0,      Xl   + gA0 + k0);
        CP16(s + TILEB + ds1,      Xl   + gA1 + k0);
        CP16(s + 2 * TILEB + ds0,  Bg_h + gB0 + k0);
        CP16(s + 2 * TILEB + ds1,  Bg_h + gB1 + k0);
        CP16(s + 3 * TILEB + ds0,  Bg_l + gB0 + k0);
        CP16(s + 3 * TILEB + ds1,  Bg_l + gB1 + k0);
        CP16(s + 4 * TILEB + ds0,  Bu_h + gB0 + k0);
        CP16(s + 4 * TILEB + ds1,  Bu_h + gB1 + k0);
        CP16(s + 5 * TILEB + ds0,  Bu_l + gB0 + k0);
        CP16(s + 5 * TILEB + ds1,  Bu_l + gB1 + k0);
        CP_COMMIT();
    };

    issue(0, 0);
    for (int kc = 0; kc < NC; kc++) {
        const int buf = kc & 1;
        if (kc + 1 < NC) { issue(kc + 1, buf ^ 1); CP_WAIT1(); }
        else             { CP_WAIT0(); }
        __syncthreads();
        const uint32_t s = sb + buf * GU_SBUF;
#pragma unroll
        for (int ks = 0; ks < 2; ks++) {
            uint32_t aH[4][4], aL[4][4];
            const uint32_t aBase = s + wm * MSTRIDE + aOff + ks * 32;
#pragma unroll
            for (int tm = 0; tm < 4; tm++) {
                const uint32_t ad = aBase + tm * 16 * MSTRIDE;
                LDSM4(aH[tm][0], aH[tm][1], aH[tm][2], aH[tm][3], ad);
                LDSM4(aL[tm][0], aL[tm][1], aL[tm][2], aL[tm][3], ad + TILEB);
            }
            const uint32_t bBase = s + 2 * TILEB + wn * MSTRIDE + bOff + ks * 32;
#pragma unroll
            for (int tn = 0; tn < 4; tn++) {
                const uint32_t bd = bBase + tn * 8 * MSTRIDE;
                uint32_t g[4], u[4];
                LDSM4(g[0], g[1], g[2], g[3], bd);              // gh0 gh1 gl0 gl1
                LDSM4(u[0], u[1], u[2], u[3], bd + 2 * TILEB);  // uh0 uh1 ul0 ul1
                // same-accumulator MMAs spaced >= 8 apart
#pragma unroll
                for (int tm = 0; tm < 4; tm++) MMA16(accG[tm][tn], aH[tm], g[0], g[1]);
#pragma unroll
                for (int tm = 0; tm < 4; tm++) MMA16(accU[tm][tn], aH[tm], u[0], u[1]);
#pragma unroll
                for (int tm = 0; tm < 4; tm++) MMA16(accG[tm][tn], aH[tm], g[2], g[3]);
#pragma unroll
                for (int tm = 0; tm < 4; tm++) MMA16(accU[tm][tn], aH[tm], u[2], u[3]);
#pragma unroll
                for (int tm = 0; tm < 4; tm++) MMA16(accG[tm][tn], aL[tm], g[0], g[1]);
#pragma unroll
                for (int tm = 0; tm < 4; tm++) MMA16(accU[tm][tn], aL[tm], u[0], u[1]);
            }
        }
        __syncthreads();
    }

    // epilogue: silu(g)*u*route_weight -> split bf16 -> H (scattered)
    const int colbase = hbase + e * fdim + bn + wn;
#pragma unroll
    for (int tm = 0; tm < 4; tm++) {
#pragma unroll
        for (int half = 0; half < 2; half++) {
            const int token = tix[bm + wm + tm * 16 + grp + half * 8];
            const float wgt = scaled ? g_W[token * NEXP + e] : 1.0f;
            const size_t rowoff = (size_t)token * KDOWN;
#pragma unroll
            for (int tn = 0; tn < 4; tn++) {
                float gv0 = accG[tm][tn][half * 2 + 0];
                float gv1 = accG[tm][tn][half * 2 + 1];
                float uv0 = accU[tm][tn][half * 2 + 0];
                float uv1 = accU[tm][tn][half * 2 + 1];
                float h0 = gv0 / (1.f + expf(-gv0)) * uv0 * wgt;
                float h1 = gv1 / (1.f + expf(-gv1)) * uv1 * wgt;
                __nv_bfloat16 hh0, hl0, hh1, hl1;
                split_bf(h0, hh0, hl0);
                split_bf(h1, hh1, hl1);
                const int col = colbase + tn * 8 + tI * 2;
                *reinterpret_cast<uint32_t*>(g_Hh + rowoff + col) = pk_bf2(hh0, hh1);
                *reinterpret_cast<uint32_t*>(g_Hl + rowoff + col) = pk_bf2(hl0, hl1);
            }
        }
    }
}

// ---------------- down HMMA GEMM (combine) -------------------------------------
#define DN_SBUF (4 * TILEB)       // 40960
#define DN_SMEM (2 * DN_SBUF)     // 81920

__global__ __launch_bounds__(256, 2)
void dn_mma(float* __restrict__ out) {
    extern __shared__ __align__(16) char smem[];
    const uint32_t sb = smem_u32(smem);
    const int tid = threadIdx.x;
    const int wid = tid >> 5, lane = tid & 31;
    const int grp = lane >> 2, tI = lane & 3;
    const int wm = (wid >> 2) * 64, wn = (wid & 3) * 32;
    const int bm = blockIdx.y * 128, bn = blockIdx.x * 128;

    const int lr = tid >> 2, lq = tid & 3;
    const uint32_t ds0 = lr * MSTRIDE + lq * 16;
    const uint32_t ds1 = (lr + 64) * MSTRIDE + lq * 16;
    const size_t gA0 = (size_t)(bm + lr) * KDOWN + lq * 8;
    const size_t gA1 = gA0 + (size_t)64 * KDOWN;
    const size_t gB0 = (size_t)(bn + lr) * KDOWN + lq * 8;
    const size_t gB1 = gB0 + (size_t)64 * KDOWN;

    const uint32_t aOff = (lane & 15) * MSTRIDE + (lane >> 4) * 16;
    const uint32_t bOff = (lane & 7) * MSTRIDE + ((lane >> 3) & 1) * 16 + (lane >> 4) * TILEB;

    float acc[4][4][4];
#pragma unroll
    for (int i = 0; i < 4; i++)
#pragma unroll
        for (int j = 0; j < 4; j++)
#pragma unroll
            for (int r = 0; r < 4; r++) acc[i][j][r] = 0.f;

    const int NC = KDOWN / BK;   // 160

    auto issue = [&](int kc, int buf) {
        const int k0 = kc * BK;
        const uint32_t s = sb + buf * DN_SBUF;
        CP16(s + ds0,              g_Hh  + gA0 + k0);
        CP16(s + ds1,              g_Hh  + gA1 + k0);
        CP16(s + TILEB + ds0,      g_Hl  + gA0 + k0);
        CP16(s + TILEB + ds1,      g_Hl  + gA1 + k0);
        CP16(s + 2 * TILEB + ds0,  g_Bdh + gB0 + k0);
        CP16(s + 2 * TILEB + ds1,  g_Bdh + gB1 + k0);
        CP16(s + 3 * TILEB + ds0,  g_Bdl + gB0 + k0);
        CP16(s + 3 * TILEB + ds1,  g_Bdl + gB1 + k0);
        CP_COMMIT();
    };

    issue(0, 0);
    for (int kc = 0; kc < NC; kc++) {
        const int buf = kc & 1;
        if (kc + 1 < NC) { issue(kc + 1, buf ^ 1); CP_WAIT1(); }
        else             { CP_WAIT0(); }
        __syncthreads();
        const uint32_t s = sb + buf * DN_SBUF;
#pragma unroll
        for (int ks = 0; ks < 2; ks++) {
            uint32_t aH[4][4], aL[4][4];
            const uint32_t aBase = s + wm * MSTRIDE + aOff + ks * 32;
#pragma unroll
            for (int tm = 0; tm < 4; tm++) {
                const uint32_t ad = aBase + tm * 16 * MSTRIDE;
                LDSM4(aH[tm][0], aH[tm][1], aH[tm][2], aH[tm][3], ad);
                LDSM4(aL[tm][0], aL[tm][1], aL[tm][2], aL[tm][3], ad + TILEB);
            }
            const uint32_t bBase = s + 2 * TILEB + wn * MSTRIDE + bOff + ks * 32;
#pragma unroll
            for (int tn = 0; tn < 4; tn++) {
                uint32_t b[4];
                LDSM4(b[0], b[1], b[2], b[3], bBase + tn * 8 * MSTRIDE);  // bh0 bh1 bl0 bl1
                // same-accumulator MMAs spaced 4 apart
#pragma unroll
                for (int tm = 0; tm < 4; tm++) MMA16(acc[tm][tn], aH[tm], b[0], b[1]);
#pragma unroll
                for (int tm = 0; tm < 4; tm++) MMA16(acc[tm][tn], aH[tm], b[2], b[3]);
#pragma unroll
                for (int tm = 0; tm < 4; tm++) MMA16(acc[tm][tn], aL[tm], b[0], b[1]);
            }
        }
        __syncthreads();
    }

#pragma unroll
    for (int tm = 0; tm < 4; tm++) {
#pragma unroll
        for (int half = 0; half < 2; half++) {
            const int token = bm + wm + tm * 16 + grp + half * 8;
#pragma unroll
            for (int tn = 0; tn < 4; tn++) {
                const int col = bn + wn + tn * 8 + tI * 2;
                float2 v = make_float2(acc[tm][tn][half * 2], acc[tm][tn][half * 2 + 1]);
                *reinterpret_cast<float2*>(out + (size_t)token * DDIM + col) = v;
            }
        }
    }
}

// ---------------- launch --------------------------------------------------------
extern "C" void kernel_launch(void* const* d_in, const int* in_sizes, int n_in,
                              void* d_out, int out_size) {
    const float* x   = (const float*)d_in[0];
    const float* rw  = (const float*)d_in[1];
    const float* wg  = (const float*)d_in[2];
    const float* wu  = (const float*)d_in[3];
    const float* wd  = (const float*)d_in[4];
    const float* wsg = (const float*)d_in[5];
    const float* wsu = (const float*)d_in[6];
    const float* wsd = (const float*)d_in[7];
    float* out = (float*)d_out;

    void *pXh, *pXl, *pBgh, *pBgl, *pBuh, *pBul, *pBsgh, *pBsgl, *pBsuh, *pBsul, *pBdh, *pBdl;
    void *pIdx, *pIdxI, *pCntp;
    cudaGetSymbolAddress(&pXh, g_Xh);     cudaGetSymbolAddress(&pXl, g_Xl);
    cudaGetSymbolAddress(&pBgh, g_Bgh);   cudaGetSymbolAddress(&pBgl, g_Bgl);
    cudaGetSymbolAddress(&pBuh, g_Buh);   cudaGetSymbolAddress(&pBul, g_Bul);
    cudaGetSymbolAddress(&pBsgh, g_Bsgh); cudaGetSymbolAddress(&pBsgl, g_Bsgl);
    cudaGetSymbolAddress(&pBsuh, g_Bsuh); cudaGetSymbolAddress(&pBsul, g_Bsul);
    cudaGetSymbolAddress(&pBdh, g_Bdh);   cudaGetSymbolAddress(&pBdl, g_Bdl);
    cudaGetSymbolAddress(&pIdx, g_idx);   cudaGetSymbolAddress(&pIdxI, g_idxI);
    cudaGetSymbolAddress(&pCntp, g_cntp);

    cudaFuncSetAttribute(gu_mma, cudaFuncAttributeMaxDynamicSharedMemorySize, GU_SMEM);
    cudaFuncSetAttribute(dn_mma, cudaFuncAttributeMaxDynamicSharedMemorySize, DN_SMEM);

    // 1: reset counters + identity list
    init_lists<<<16, 256>>>();
    // 2: router + compacted expert token lists
    router_kernel<<<T_TOK / 4, 128>>>(x, rw);
    // 3: pad lists to 128-multiples
    pad_idx<<<NEXP, 128>>>();
    // 4: activation split
    cvt_split<<<T_TOK * DDIM / 1024, 256>>>(x, (__nv_bfloat16*)pXh, (__nv_bfloat16*)pXl);
    // 5: zero H (routed slots default to 0)
    zeroH<<<(T_TOK * (size_t)KDOWN) / (256 * 8), 256>>>();
    // 6: w_gate + w_up transpose/split
    dim3 tb(32, 8);
    prepA<<<dim3(16, 32, 16), tb>>>(wg, wu,
        (__nv_bfloat16*)pBgh, (__nv_bfloat16*)pBgl,
        (__nv_bfloat16*)pBuh, (__nv_bfloat16*)pBul);
    // 7: shared weights + down weights transpose/split
    prepB<<<dim3(32, 32, 11), tb>>>(wsg, wsu, wd, wsd,
        (__nv_bfloat16*)pBsgh, (__nv_bfloat16*)pBsgl,
        (__nv_bfloat16*)pBsuh, (__nv_bfloat16*)pBsul,
        (__nv_bfloat16*)pBdh,  (__nv_bfloat16*)pBdl);
    // 8: shared expert gate+up (dense, identity list) -> H[:, 4096:5120]
    gu_mma<<<dim3(FSDIM / 128, T_TOK / 128, 1), 256, GU_SMEM>>>(
        (const __nv_bfloat16*)pXh, (const __nv_bfloat16*)pXl,
        (const __nv_bfloat16*)pBsgh, (const __nv_bfloat16*)pBsgl,
        (const __nv_bfloat16*)pBsuh, (const __nv_bfloat16*)pBsul,
        (const int*)pIdxI, 0, nullptr,
        FSDIM, NEXP * FDIM, 0);
    // 9: routed experts gate+up (gathered ~3072 tokens/expert) -> H[:, 0:4096]
    gu_mma<<<dim3(FDIM / 128, T_TOK / 128, NEXP), 256, GU_SMEM>>>(
        (const __nv_bfloat16*)pXh, (const __nv_bfloat16*)pXl,
        (const __nv_bfloat16*)pBgh, (const __nv_bfloat16*)pBgl,
        (const __nv_bfloat16*)pBuh, (const __nv_bfloat16*)pBul,
        (const int*)pIdx, IDXSTR, (const int*)pCntp,
        FDIM, 0, 1);
    // 10: down + weighted combine + shared add
    dn_mma<<<dim3(DDIM / 128, T_TOK / 128), 256, DN_SMEM>>>(out);
}

// round 7
// speedup vs baseline: 3.3652x; 1.4241x over previous
#include <cuda_runtime.h>
#include <cuda_fp16.h>
#include <math.h>
#include <stdint.h>

#define T_TOK 4096
#define DDIM  1024
#define NEXP  8
#define FDIM  512
#define FSDIM 1024
#define KDOWN 5120
#define TOPK  6

#define BK 32
#define MSTRIDE 80                 // 64 data + 16 pad: 16B-aligned rows, ldmatrix conflict-free
#define TILEB (128 * MSTRIDE)      // 10240 bytes per 128-row tile
#define IDXSTR 4224

// ---------------- scratch ----------------------------------------------------
__device__ float g_W[T_TOK * NEXP];
__device__ int   g_idx[NEXP * IDXSTR];
__device__ int   g_idxI[T_TOK];
__device__ int   g_cnt[NEXP];
__device__ int   g_cntp[NEXP];
__device__ __half g_Xh[T_TOK * DDIM];
__device__ __half g_Xl[T_TOK * DDIM];
__device__ __half g_Bg[NEXP * FDIM * DDIM];      // single fp16 weights, K-major [n][k]
__device__ __half g_Bu[NEXP * FDIM * DDIM];
__device__ __half g_Bsg[FSDIM * DDIM];
__device__ __half g_Bsu[FSDIM * DDIM];
__device__ __half g_Bd[DDIM * KDOWN];            // [n=1024][k=5120]
__device__ __half g_Hh[(size_t)T_TOK * KDOWN];
__device__ __half g_Hl[(size_t)T_TOK * KDOWN];

// ---------------- helpers ----------------------------------------------------
__device__ __forceinline__ uint32_t smem_u32(const void* p) {
    uint32_t a;
    asm("{ .reg .u64 t; cvta.to.shared.u64 t, %1; cvt.u32.u64 %0, t; }"
        : "=r"(a) : "l"(p));
    return a;
}

#define CP16(dst, src) \
    asm volatile("cp.async.cg.shared.global [%0], [%1], 16;" :: "r"(dst), "l"(src) : "memory")
#define CP_COMMIT() asm volatile("cp.async.commit_group;" ::: "memory")
#define CP_WAIT1()  asm volatile("cp.async.wait_group 1;" ::: "memory")
#define CP_WAIT0()  asm volatile("cp.async.wait_group 0;" ::: "memory")

#define LDSM4(r0, r1, r2, r3, a) \
    asm volatile("ldmatrix.sync.aligned.m8n8.x4.shared.b16 {%0,%1,%2,%3}, [%4];" \
        : "=r"(r0), "=r"(r1), "=r"(r2), "=r"(r3) : "r"(a))

#define MMA16(d, a, b0, b1) \
    asm volatile( \
        "mma.sync.aligned.m16n8k16.row.col.f32.f16.f16.f32 " \
        "{%0,%1,%2,%3},{%4,%5,%6,%7},{%8,%9},{%0,%1,%2,%3};" \
        : "+f"((d)[0]), "+f"((d)[1]), "+f"((d)[2]), "+f"((d)[3]) \
        : "r"((a)[0]), "r"((a)[1]), "r"((a)[2]), "r"((a)[3]), "r"(b0), "r"(b1))

__device__ __forceinline__ uint32_t pk_h2(__half a, __half b) {
    __half2 t = __halves2half2(a, b);
    return *reinterpret_cast<uint32_t*>(&t);
}
__device__ __forceinline__ void split_h(float v, __half& h, __half& l) {
    h = __float2half_rn(v);
    l = __float2half_rn(v - __half2float(h));
}

// ---------------- init ---------------------------------------------------------
__global__ void init_lists() {
    int t = blockIdx.x * 256 + threadIdx.x;
    if (t < T_TOK) g_idxI[t] = t;
    if (t < NEXP)  g_cnt[t] = 0;
}

// ---------------- router + per-expert token lists ------------------------------
__global__ void router_kernel(const float* __restrict__ x,
                              const float* __restrict__ rw) {
    int gw = (blockIdx.x * blockDim.x + threadIdx.x) >> 5;
    int lane = threadIdx.x & 31;
    if (gw >= T_TOK) return;
    const float* xr = x + (size_t)gw * DDIM;
    float acc[NEXP];
#pragma unroll
    for (int e = 0; e < NEXP; e++) acc[e] = 0.f;
    for (int d = lane; d < DDIM; d += 32) {
        float xv = xr[d];
        const float4* r4 = reinterpret_cast<const float4*>(rw + (size_t)d * NEXP);
        float4 r0 = r4[0], r1 = r4[1];
        acc[0] = fmaf(xv, r0.x, acc[0]); acc[1] = fmaf(xv, r0.y, acc[1]);
        acc[2] = fmaf(xv, r0.z, acc[2]); acc[3] = fmaf(xv, r0.w, acc[3]);
        acc[4] = fmaf(xv, r1.x, acc[4]); acc[5] = fmaf(xv, r1.y, acc[5]);
        acc[6] = fmaf(xv, r1.z, acc[6]); acc[7] = fmaf(xv, r1.w, acc[7]);
    }
#pragma unroll
    for (int off = 16; off > 0; off >>= 1)
#pragma unroll
        for (int e = 0; e < NEXP; e++)
            acc[e] += __shfl_xor_sync(0xffffffffu, acc[e], off);
    if (lane == 0) {
        float m = acc[0];
#pragma unroll
        for (int e = 1; e < NEXP; e++) m = fmaxf(m, acc[e]);
        float p[NEXP], s = 0.f;
#pragma unroll
        for (int e = 0; e < NEXP; e++) { p[e] = expf(acc[e] - m); s += p[e]; }
        float inv = 1.f / s;
#pragma unroll
        for (int e = 0; e < NEXP; e++) p[e] *= inv;
#pragma unroll
        for (int e = 0; e < NEXP; e++) {
            int rank = 0;
#pragma unroll
            for (int e2 = 0; e2 < NEXP; e2++)
                rank += (p[e2] > p[e] || (p[e2] == p[e] && e2 < e)) ? 1 : 0;
            bool sel = (rank < TOPK);
            g_W[gw * NEXP + e] = sel ? p[e] : 0.f;
            if (sel) {
                int pos = atomicAdd(&g_cnt[e], 1);
                g_idx[e * IDXSTR + pos] = gw;
            }
        }
    }
}

__global__ void pad_idx() {
    int e = blockIdx.x;
    int cnt = g_cnt[e];
    int cntp = (cnt + 127) & ~127;
    if (threadIdx.x == 0) g_cntp[e] = cntp;
    if (cnt == 0) return;
    int last = g_idx[e * IDXSTR + cnt - 1];
    for (int i = cnt + threadIdx.x; i < cntp; i += 128)
        g_idx[e * IDXSTR + i] = last;
}

__global__ void zeroH() {
    size_t i = ((size_t)blockIdx.x * 256 + threadIdx.x) * 8;
    uint4 z = make_uint4(0, 0, 0, 0);
    *reinterpret_cast<uint4*>(g_Hh + i) = z;
    *reinterpret_cast<uint4*>(g_Hl + i) = z;
}

// ---------------- conversions ---------------------------------------------------
__global__ void cvt_split(const float* __restrict__ src,
                          __half* __restrict__ dh, __half* __restrict__ dl) {
    int i = (blockIdx.x * 256 + threadIdx.x) * 4;
    float4 v = *reinterpret_cast<const float4*>(src + i);
    __half h0, l0, h1, l1, h2, l2, h3, l3;
    split_h(v.x, h0, l0); split_h(v.y, h1, l1);
    split_h(v.z, h2, l2); split_h(v.w, h3, l3);
    uint2 ph, pl;
    ph.x = pk_h2(h0, h1); ph.y = pk_h2(h2, h3);
    pl.x = pk_h2(l0, l1); pl.y = pk_h2(l2, l3);
    *reinterpret_cast<uint2*>(dh + i) = ph;
    *reinterpret_cast<uint2*>(dl + i) = pl;
}

__device__ __forceinline__ void tpose_body(
    const float* __restrict__ src, __half* __restrict__ dst,
    int C, long long zs, long long zd, int rs) {
    __shared__ float t[32][33];
    int c0 = blockIdx.x * 32, r0 = blockIdx.y * 32;
    int tx = threadIdx.x, ty = threadIdx.y;
#pragma unroll
    for (int k = 0; k < 32; k += 8)
        t[ty + k][tx] = src[zs + (long long)(r0 + ty + k) * C + c0 + tx];
    __syncthreads();
#pragma unroll
    for (int k = 0; k < 32; k += 8) {
        float v = t[tx][ty + k];
        int n = c0 + ty + k, r = r0 + tx;
        dst[zd + (long long)n * rs + r] = __float2half_rn(v);
    }
}

__global__ void prepA(const float* __restrict__ wg, const float* __restrict__ wu,
                      __half* bg, __half* bu) {
    int z = blockIdx.z;
    if (z < 8)
        tpose_body(wg, bg, FDIM, (long long)z * DDIM * FDIM, (long long)z * FDIM * DDIM, DDIM);
    else
        tpose_body(wu, bu, FDIM, (long long)(z - 8) * DDIM * FDIM, (long long)(z - 8) * FDIM * DDIM, DDIM);
}

__global__ void prepB(const float* __restrict__ wsg, const float* __restrict__ wsu,
                      const float* __restrict__ wd,  const float* __restrict__ wsd,
                      __half* bsg, __half* bsu, __half* bd) {
    int z = blockIdx.z;
    if (z == 0)      tpose_body(wsg, bsg, FSDIM, 0, 0, DDIM);
    else if (z == 1) tpose_body(wsu, bsu, FSDIM, 0, 0, DDIM);
    else if (z <= 9) {
        if (blockIdx.y >= 16) return;
        int e = z - 2;
        tpose_body(wd, bd, DDIM, (long long)e * FDIM * DDIM, (long long)e * FDIM, KDOWN);
    } else
        tpose_body(wsd, bd, DDIM, 0, (long long)NEXP * FDIM, KDOWN);
}

// ---------------- fused gate+up fp16 MMA GEMM (2-pass, gathered) ----------------
// tiles per buffer: Ah, Al, Bg, Bu
#define GU_SBUF (4 * TILEB)       // 40960
#define GU_SMEM (2 * GU_SBUF)     // 81920

__global__ __launch_bounds__(256, 1)
void gu_mma(const __half* __restrict__ Xh, const __half* __restrict__ Xl,
            const __half* __restrict__ Gw, const __half* __restrict__ Uw,
            const int* __restrict__ tix_base, int tix_stride,
            const int* __restrict__ cntp,
            int fdim, int hbase, int scaled) {
    extern __shared__ __align__(16) char smem[];
    const uint32_t sb = smem_u32(smem);
    const int tid = threadIdx.x;
    const int wid = tid >> 5, lane = tid & 31;
    const int grp = lane >> 2, tI = lane & 3;
    const int wm = (wid >> 2) * 64, wn = (wid & 3) * 32;
    const int bm = blockIdx.y * 128, bn = blockIdx.x * 128;
    const int e = blockIdx.z;
    if (cntp && bm >= cntp[e]) return;
    const int* tix = tix_base + (size_t)e * tix_stride;
    const size_t beoff = (size_t)e * fdim * DDIM;
    const __half* Bg = Gw + beoff;
    const __half* Bu = Uw + beoff;

    const int lr = tid >> 2, lq = tid & 3;
    const uint32_t ds0 = lr * MSTRIDE + lq * 16;
    const uint32_t ds1 = (lr + 64) * MSTRIDE + lq * 16;
    const int tokA0 = tix[bm + lr];
    const int tokA1 = tix[bm + lr + 64];
    const size_t gA0 = (size_t)tokA0 * DDIM + lq * 8;
    const size_t gA1 = (size_t)tokA1 * DDIM + lq * 8;
    const size_t gB0 = (size_t)(bn + lr) * DDIM + lq * 8;
    const size_t gB1 = gB0 + (size_t)64 * DDIM;

    const uint32_t aOff = (lane & 15) * MSTRIDE + (lane >> 4) * 16;
    // B ldmatrix: mats = [n0-7 k0:8 | n0-7 k8:16 | n8-15 k0:8 | n8-15 k8:16]
    const uint32_t bOff = (lane & 7) * MSTRIDE + ((lane >> 3) & 1) * 16
                        + (lane >> 4) * 8 * MSTRIDE;

    float accG[4][4][4], accU[4][4][4];
#pragma unroll
    for (int i = 0; i < 4; i++)
#pragma unroll
        for (int j = 0; j < 4; j++)
#pragma unroll
            for (int r = 0; r < 4; r++) { accG[i][j][r] = 0.f; accU[i][j][r] = 0.f; }

    const int NC = DDIM / BK;   // 32

    auto issue = [&](int kc, int buf) {
        const int k0 = kc * BK;
        const uint32_t s = sb + buf * GU_SBUF;
        CP16(s + ds0,             Xh + gA0 + k0);
        CP16(s + ds1,             Xh + gA1 + k0);
        CP16(s + TILEB + ds0,     Xl + gA0 + k0);
        CP16(s + TILEB + ds1,     Xl + gA1 + k0);
        CP16(s + 2 * TILEB + ds0, Bg + gB0 + k0);
        CP16(s + 2 * TILEB + ds1, Bg + gB1 + k0);
        CP16(s + 3 * TILEB + ds0, Bu + gB0 + k0);
        CP16(s + 3 * TILEB + ds1, Bu + gB1 + k0);
        CP_COMMIT();
    };

    issue(0, 0);
    for (int kc = 0; kc < NC; kc++) {
        const int buf = kc & 1;
        if (kc + 1 < NC) { issue(kc + 1, buf ^ 1); CP_WAIT1(); }
        else             { CP_WAIT0(); }
        __syncthreads();
        const uint32_t s = sb + buf * GU_SBUF;
#pragma unroll
        for (int ks = 0; ks < 2; ks++) {
            uint32_t aH[4][4], aL[4][4];
            const uint32_t aBase = s + wm * MSTRIDE + aOff + ks * 32;
#pragma unroll
            for (int tm = 0; tm < 4; tm++) {
                const uint32_t ad = aBase + tm * 16 * MSTRIDE;
                LDSM4(aH[tm][0], aH[tm][1], aH[tm][2], aH[tm][3], ad);
                LDSM4(aL[tm][0], aL[tm][1], aL[tm][2], aL[tm][3], ad + TILEB);
            }
            const uint32_t bgB = s + 2 * TILEB + wn * MSTRIDE + bOff + ks * 32;
            const uint32_t buB = s + 3 * TILEB + wn * MSTRIDE + bOff + ks * 32;
#pragma unroll
            for (int tn2 = 0; tn2 < 2; tn2++) {
                uint32_t g[4], u[4];
                LDSM4(g[0], g[1], g[2], g[3], bgB + tn2 * 16 * MSTRIDE);
                LDSM4(u[0], u[1], u[2], u[3], buB + tn2 * 16 * MSTRIDE);
                const int tn = tn2 * 2;
#pragma unroll
                for (int tm = 0; tm < 4; tm++) MMA16(accG[tm][tn],     aH[tm], g[0], g[1]);
#pragma unroll
                for (int tm = 0; tm < 4; tm++) MMA16(accU[tm][tn],     aH[tm], u[0], u[1]);
#pragma unroll
                for (int tm = 0; tm < 4; tm++) MMA16(accG[tm][tn + 1], aH[tm], g[2], g[3]);
#pragma unroll
                for (int tm = 0; tm < 4; tm++) MMA16(accU[tm][tn + 1], aH[tm], u[2], u[3]);
#pragma unroll
                for (int tm = 0; tm < 4; tm++) MMA16(accG[tm][tn],     aL[tm], g[0], g[1]);
#pragma unroll
                for (int tm = 0; tm < 4; tm++) MMA16(accU[tm][tn],     aL[tm], u[0], u[1]);
#pragma unroll
                for (int tm = 0; tm < 4; tm++) MMA16(accG[tm][tn + 1], aL[tm], g[2], g[3]);
#pragma unroll
                for (int tm = 0; tm < 4; tm++) MMA16(accU[tm][tn + 1], aL[tm], u[2], u[3]);
            }
        }
        __syncthreads();
    }

    // epilogue: silu(g)*u*route_weight -> split fp16 -> H (scattered)
    const int colbase = hbase + e * fdim + bn + wn;
#pragma unroll
    for (int tm = 0; tm < 4; tm++) {
#pragma unroll
        for (int half = 0; half < 2; half++) {
            const int token = tix[bm + wm + tm * 16 + grp + half * 8];
            const float wgt = scaled ? g_W[token * NEXP + e] : 1.0f;
            const size_t rowoff = (size_t)token * KDOWN;
#pragma unroll
            for (int tn = 0; tn < 4; tn++) {
                float gv0 = accG[tm][tn][half * 2 + 0];
                float gv1 = accG[tm][tn][half * 2 + 1];
                float uv0 = accU[tm][tn][half * 2 + 0];
                float uv1 = accU[tm][tn][half * 2 + 1];
                float h0 = gv0 / (1.f + expf(-gv0)) * uv0 * wgt;
                float h1 = gv1 / (1.f + expf(-gv1)) * uv1 * wgt;
                __half hh0, hl0, hh1, hl1;
                split_h(h0, hh0, hl0);
                split_h(h1, hh1, hl1);
                const int col = colbase + tn * 8 + tI * 2;
                *reinterpret_cast<uint32_t*>(g_Hh + rowoff + col) = pk_h2(hh0, hh1);
                *reinterpret_cast<uint32_t*>(g_Hl + rowoff + col) = pk_h2(hl0, hl1);
            }
        }
    }
}

// ---------------- down fp16 MMA GEMM (2-pass, combine) ---------------------------
// tiles per buffer: Hh, Hl, Bd
#define DN_SBUF (3 * TILEB)       // 30720
#define DN_SMEM (2 * DN_SBUF)     // 61440

__global__ __launch_bounds__(256, 2)
void dn_mma(float* __restrict__ out) {
    extern __shared__ __align__(16) char smem[];
    const uint32_t sb = smem_u32(smem);
    const int tid = threadIdx.x;
    const int wid = tid >> 5, lane = tid & 31;
    const int grp = lane >> 2, tI = lane & 3;
    const int wm = (wid >> 2) * 64, wn = (wid & 3) * 32;
    const int bm = blockIdx.y * 128, bn = blockIdx.x * 128;

    const int lr = tid >> 2, lq = tid & 3;
    const uint32_t ds0 = lr * MSTRIDE + lq * 16;
    const uint32_t ds1 = (lr + 64) * MSTRIDE + lq * 16;
    const size_t gA0 = (size_t)(bm + lr) * KDOWN + lq * 8;
    const size_t gA1 = gA0 + (size_t)64 * KDOWN;
    const size_t gB0 = (size_t)(bn + lr) * KDOWN + lq * 8;
    const size_t gB1 = gB0 + (size_t)64 * KDOWN;

    const uint32_t aOff = (lane & 15) * MSTRIDE + (lane >> 4) * 16;
    const uint32_t bOff = (lane & 7) * MSTRIDE + ((lane >> 3) & 1) * 16
                        + (lane >> 4) * 8 * MSTRIDE;

    float acc[4][4][4];
#pragma unroll
    for (int i = 0; i < 4; i++)
#pragma unroll
        for (int j = 0; j < 4; j++)
#pragma unroll
            for (int r = 0; r < 4; r++) acc[i][j][r] = 0.f;

    const int NC = KDOWN / BK;   // 160

    auto issue = [&](int kc, int buf) {
        const int k0 = kc * BK;
        const uint32_t s = sb + buf * DN_SBUF;
        CP16(s + ds0,             g_Hh + gA0 + k0);
        CP16(s + ds1,             g_Hh + gA1 + k0);
        CP16(s + TILEB + ds0,     g_Hl + gA0 + k0);
        CP16(s + TILEB + ds1,     g_Hl + gA1 + k0);
        CP16(s + 2 * TILEB + ds0, g_Bd + gB0 + k0);
        CP16(s + 2 * TILEB + ds1, g_Bd + gB1 + k0);
        CP_COMMIT();
    };

    issue(0, 0);
    for (int kc = 0; kc < NC; kc++) {
        const int buf = kc & 1;
        if (kc + 1 < NC) { issue(kc + 1, buf ^ 1); CP_WAIT1(); }
        else             { CP_WAIT0(); }
        __syncthreads();
        const uint32_t s = sb + buf * DN_SBUF;
#pragma unroll
        for (int ks = 0; ks < 2; ks++) {
            uint32_t aH[4][4], aL[4][4];
            const uint32_t aBase = s + wm * MSTRIDE + aOff + ks * 32;
#pragma unroll
            for (int tm = 0; tm < 4; tm++) {
                const uint32_t ad = aBase + tm * 16 * MSTRIDE;
                LDSM4(aH[tm][0], aH[tm][1], aH[tm][2], aH[tm][3], ad);
                LDSM4(aL[tm][0], aL[tm][1], aL[tm][2], aL[tm][3], ad + TILEB);
            }
            const uint32_t bB = s + 2 * TILEB + wn * MSTRIDE + bOff + ks * 32;
#pragma unroll
            for (int tn2 = 0; tn2 < 2; tn2++) {
                uint32_t b[4];
                LDSM4(b[0], b[1], b[2], b[3], bB + tn2 * 16 * MSTRIDE);
                const int tn = tn2 * 2;
#pragma unroll
                for (int tm = 0; tm < 4; tm++) MMA16(acc[tm][tn],     aH[tm], b[0], b[1]);
#pragma unroll
                for (int tm = 0; tm < 4; tm++) MMA16(acc[tm][tn + 1], aH[tm], b[2], b[3]);
#pragma unroll
                for (int tm = 0; tm < 4; tm++) MMA16(acc[tm][tn],     aL[tm], b[0], b[1]);
#pragma unroll
                for (int tm = 0; tm < 4; tm++) MMA16(acc[tm][tn + 1], aL[tm], b[2], b[3]);
            }
        }
        __syncthreads();
    }

#pragma unroll
    for (int tm = 0; tm < 4; tm++) {
#pragma unroll
        for (int half = 0; half < 2; half++) {
            const int token = bm + wm + tm * 16 + grp + half * 8;
#pragma unroll
            for (int tn = 0; tn < 4; tn++) {
                const int col = bn + wn + tn * 8 + tI * 2;
                float2 v = make_float2(acc[tm][tn][half * 2], acc[tm][tn][half * 2 + 1]);
                *reinterpret_cast<float2*>(out + (size_t)token * DDIM + col) = v;
            }
        }
    }
}

// ---------------- launch ----------------------------------------------------------
extern "C" void kernel_launch(void* const* d_in, const int* in_sizes, int n_in,
                              void* d_out, int out_size) {
    const float* x   = (const float*)d_in[0];
    const float* rw  = (const float*)d_in[1];
    const float* wg  = (const float*)d_in[2];
    const float* wu  = (const float*)d_in[3];
    const float* wd  = (const float*)d_in[4];
    const float* wsg = (const float*)d_in[5];
    const float* wsu = (const float*)d_in[6];
    const float* wsd = (const float*)d_in[7];
    float* out = (float*)d_out;

    void *pXh, *pXl, *pBg, *pBu, *pBsg, *pBsu, *pBd, *pIdx, *pIdxI, *pCntp;
    cudaGetSymbolAddress(&pXh, g_Xh);   cudaGetSymbolAddress(&pXl, g_Xl);
    cudaGetSymbolAddress(&pBg, g_Bg);   cudaGetSymbolAddress(&pBu, g_Bu);
    cudaGetSymbolAddress(&pBsg, g_Bsg); cudaGetSymbolAddress(&pBsu, g_Bsu);
    cudaGetSymbolAddress(&pBd, g_Bd);
    cudaGetSymbolAddress(&pIdx, g_idx); cudaGetSymbolAddress(&pIdxI, g_idxI);
    cudaGetSymbolAddress(&pCntp, g_cntp);

    cudaFuncSetAttribute(gu_mma, cudaFuncAttributeMaxDynamicSharedMemorySize, GU_SMEM);
    cudaFuncSetAttribute(dn_mma, cudaFuncAttributeMaxDynamicSharedMemorySize, DN_SMEM);

    init_lists<<<16, 256>>>();
    router_kernel<<<T_TOK / 4, 128>>>(x, rw);
    pad_idx<<<NEXP, 128>>>();
    cvt_split<<<T_TOK * DDIM / 1024, 256>>>(x, (__half*)pXh, (__half*)pXl);
    zeroH<<<(T_TOK * (size_t)KDOWN) / (256 * 8), 256>>>();
    dim3 tb(32, 8);
    prepA<<<dim3(16, 32, 16), tb>>>(wg, wu, (__half*)pBg, (__half*)pBu);
    prepB<<<dim3(32, 32, 11), tb>>>(wsg, wsu, wd, wsd,
        (__half*)pBsg, (__half*)pBsu, (__half*)pBd);
    // shared expert gate+up (dense) -> H[:, 4096:5120]
    gu_mma<<<dim3(FSDIM / 128, T_TOK / 128, 1), 256, GU_SMEM>>>(
        (const __half*)pXh, (const __half*)pXl,
        (const __half*)pBsg, (const __half*)pBsu,
        (const int*)pIdxI, 0, nullptr,
        FSDIM, NEXP * FDIM, 0);
    // routed experts gate+up (gathered) -> H[:, 0:4096]
    gu_mma<<<dim3(FDIM / 128, T_TOK / 128, NEXP), 256, GU_SMEM>>>(
        (const __half*)pXh, (const __half*)pXl,
        (const __half*)pBg, (const __half*)pBu,
        (const int*)pIdx, IDXSTR, (const int*)pCntp,
        FDIM, 0, 1);
    // down + weighted combine + shared add
    dn_mma<<<dim3(DDIM / 128, T_TOK / 128), 256, DN_SMEM>>>(out);
}

// round 8
// speedup vs baseline: 5.1861x; 1.5411x over previous
#include <cuda_runtime.h>
#include <cuda_fp16.h>
#include <math.h>
#include <stdint.h>

#define T_TOK 4096
#define DDIM  1024
#define NEXP  8
#define FDIM  512
#define FSDIM 1024
#define KDOWN 5120
#define TOPK  6

#define BK 32
#define MSTRIDE 80                 // 64 data + 16 pad: 16B-aligned rows, ldmatrix conflict-free
#define TILEB (128 * MSTRIDE)      // 10240 bytes per 128-row tile
#define IDXSTR 4224

// ---------------- scratch ----------------------------------------------------
__device__ float g_W[T_TOK * NEXP];
__device__ int   g_idx[NEXP * IDXSTR];
__device__ int   g_idxI[T_TOK];
__device__ int   g_cnt[NEXP];
__device__ int   g_cntp[NEXP];
__device__ __half g_X[T_TOK * DDIM];
__device__ __half g_Bg[NEXP * FDIM * DDIM];      // fp16 weights, K-major [n][k]
__device__ __half g_Bu[NEXP * FDIM * DDIM];
__device__ __half g_Bsg[FSDIM * DDIM];
__device__ __half g_Bsu[FSDIM * DDIM];
__device__ __half g_Bd[DDIM * KDOWN];            // [n=1024][k=5120]
__device__ __half g_H[(size_t)T_TOK * KDOWN];

// ---------------- helpers ----------------------------------------------------
__device__ __forceinline__ uint32_t smem_u32(const void* p) {
    uint32_t a;
    asm("{ .reg .u64 t; cvta.to.shared.u64 t, %1; cvt.u32.u64 %0, t; }"
        : "=r"(a) : "l"(p));
    return a;
}

#define CP16(dst, src) \
    asm volatile("cp.async.cg.shared.global [%0], [%1], 16;" :: "r"(dst), "l"(src) : "memory")
#define CP_COMMIT() asm volatile("cp.async.commit_group;" ::: "memory")
#define CP_WAIT1()  asm volatile("cp.async.wait_group 1;" ::: "memory")
#define CP_WAIT0()  asm volatile("cp.async.wait_group 0;" ::: "memory")

#define LDSM4(r0, r1, r2, r3, a) \
    asm volatile("ldmatrix.sync.aligned.m8n8.x4.shared.b16 {%0,%1,%2,%3}, [%4];" \
        : "=r"(r0), "=r"(r1), "=r"(r2), "=r"(r3) : "r"(a))

#define MMA16(d, a, b0, b1) \
    asm volatile( \
        "mma.sync.aligned.m16n8k16.row.col.f32.f16.f16.f32 " \
        "{%0,%1,%2,%3},{%4,%5,%6,%7},{%8,%9},{%0,%1,%2,%3};" \
        : "+f"((d)[0]), "+f"((d)[1]), "+f"((d)[2]), "+f"((d)[3]) \
        : "r"((a)[0]), "r"((a)[1]), "r"((a)[2]), "r"((a)[3]), "r"(b0), "r"(b1))

__device__ __forceinline__ uint32_t pk_h2(__half a, __half b) {
    __half2 t = __halves2half2(a, b);
    return *reinterpret_cast<uint32_t*>(&t);
}

// ---------------- init ---------------------------------------------------------
__global__ void init_lists() {
    int t = blockIdx.x * 256 + threadIdx.x;
    if (t < T_TOK) g_idxI[t] = t;
    if (t < NEXP)  g_cnt[t] = 0;
}

// ---------------- router + per-expert token lists ------------------------------
__global__ void router_kernel(const float* __restrict__ x,
                              const float* __restrict__ rw) {
    int gw = (blockIdx.x * blockDim.x + threadIdx.x) >> 5;
    int lane = threadIdx.x & 31;
    if (gw >= T_TOK) return;
    const float* xr = x + (size_t)gw * DDIM;
    float acc[NEXP];
#pragma unroll
    for (int e = 0; e < NEXP; e++) acc[e] = 0.f;
    for (int d = lane; d < DDIM; d += 32) {
        float xv = xr[d];
        const float4* r4 = reinterpret_cast<const float4*>(rw + (size_t)d * NEXP);
        float4 r0 = r4[0], r1 = r4[1];
        acc[0] = fmaf(xv, r0.x, acc[0]); acc[1] = fmaf(xv, r0.y, acc[1]);
        acc[2] = fmaf(xv, r0.z, acc[2]); acc[3] = fmaf(xv, r0.w, acc[3]);
        acc[4] = fmaf(xv, r1.x, acc[4]); acc[5] = fmaf(xv, r1.y, acc[5]);
        acc[6] = fmaf(xv, r1.z, acc[6]); acc[7] = fmaf(xv, r1.w, acc[7]);
    }
#pragma unroll
    for (int off = 16; off > 0; off >>= 1)
#pragma unroll
        for (int e = 0; e < NEXP; e++)
            acc[e] += __shfl_xor_sync(0xffffffffu, acc[e], off);
    if (lane == 0) {
        float m = acc[0];
#pragma unroll
        for (int e = 1; e < NEXP; e++) m = fmaxf(m, acc[e]);
        float p[NEXP], s = 0.f;
#pragma unroll
        for (int e = 0; e < NEXP; e++) { p[e] = expf(acc[e] - m); s += p[e]; }
        float inv = 1.f / s;
#pragma unroll
        for (int e = 0; e < NEXP; e++) p[e] *= inv;
#pragma unroll
        for (int e = 0; e < NEXP; e++) {
            int rank = 0;
#pragma unroll
            for (int e2 = 0; e2 < NEXP; e2++)
                rank += (p[e2] > p[e] || (p[e2] == p[e] && e2 < e)) ? 1 : 0;
            bool sel = (rank < TOPK);
            g_W[gw * NEXP + e] = sel ? p[e] : 0.f;
            if (sel) {
                int pos = atomicAdd(&g_cnt[e], 1);
                g_idx[e * IDXSTR + pos] = gw;
            }
        }
    }
}

__global__ void pad_idx() {
    int e = blockIdx.x;
    int cnt = g_cnt[e];
    int cntp = (cnt + 127) & ~127;
    if (threadIdx.x == 0) g_cntp[e] = cntp;
    if (cnt == 0) return;
    int last = g_idx[e * IDXSTR + cnt - 1];
    for (int i = cnt + threadIdx.x; i < cntp; i += 128)
        g_idx[e * IDXSTR + i] = last;
}

__global__ void zeroH() {
    size_t i = ((size_t)blockIdx.x * 256 + threadIdx.x) * 8;
    *reinterpret_cast<uint4*>(g_H + i) = make_uint4(0, 0, 0, 0);
}

// ---------------- conversions ---------------------------------------------------
__global__ void cvt(const float* __restrict__ src, __half* __restrict__ dst) {
    int i = (blockIdx.x * 256 + threadIdx.x) * 4;
    float4 v = *reinterpret_cast<const float4*>(src + i);
    uint2 p;
    p.x = pk_h2(__float2half_rn(v.x), __float2half_rn(v.y));
    p.y = pk_h2(__float2half_rn(v.z), __float2half_rn(v.w));
    *reinterpret_cast<uint2*>(dst + i) = p;
}

__device__ __forceinline__ void tpose_body(
    const float* __restrict__ src, __half* __restrict__ dst,
    int C, long long zs, long long zd, int rs) {
    __shared__ float t[32][33];
    int c0 = blockIdx.x * 32, r0 = blockIdx.y * 32;
    int tx = threadIdx.x, ty = threadIdx.y;
#pragma unroll
    for (int k = 0; k < 32; k += 8)
        t[ty + k][tx] = src[zs + (long long)(r0 + ty + k) * C + c0 + tx];
    __syncthreads();
#pragma unroll
    for (int k = 0; k < 32; k += 8) {
        float v = t[tx][ty + k];
        int n = c0 + ty + k, r = r0 + tx;
        dst[zd + (long long)n * rs + r] = __float2half_rn(v);
    }
}

__global__ void prepA(const float* __restrict__ wg, const float* __restrict__ wu,
                      __half* bg, __half* bu) {
    int z = blockIdx.z;
    if (z < 8)
        tpose_body(wg, bg, FDIM, (long long)z * DDIM * FDIM, (long long)z * FDIM * DDIM, DDIM);
    else
        tpose_body(wu, bu, FDIM, (long long)(z - 8) * DDIM * FDIM, (long long)(z - 8) * FDIM * DDIM, DDIM);
}

__global__ void prepB(const float* __restrict__ wsg, const float* __restrict__ wsu,
                      const float* __restrict__ wd,  const float* __restrict__ wsd,
                      __half* bsg, __half* bsu, __half* bd) {
    int z = blockIdx.z;
    if (z == 0)      tpose_body(wsg, bsg, FSDIM, 0, 0, DDIM);
    else if (z == 1) tpose_body(wsu, bsu, FSDIM, 0, 0, DDIM);
    else if (z <= 9) {
        if (blockIdx.y >= 16) return;
        int e = z - 2;
        tpose_body(wd, bd, DDIM, (long long)e * FDIM * DDIM, (long long)e * FDIM, KDOWN);
    } else
        tpose_body(wsd, bd, DDIM, 0, (long long)NEXP * FDIM, KDOWN);
}

// ---------------- fused gate+up fp16 MMA GEMM (single-pass, gathered) -----------
// tiles per buffer: A, Bg, Bu
#define GU_SBUF (3 * TILEB)       // 30720
#define GU_SMEM (2 * GU_SBUF)     // 61440

__global__ __launch_bounds__(256, 1)
void gu_mma(const __half* __restrict__ X,
            const __half* __restrict__ Gw, const __half* __restrict__ Uw,
            const int* __restrict__ tix_base, int tix_stride,
            const int* __restrict__ cntp,
            int fdim, int hbase, int scaled) {
    extern __shared__ __align__(16) char smem[];
    const uint32_t sb = smem_u32(smem);
    const int tid = threadIdx.x;
    const int wid = tid >> 5, lane = tid & 31;
    const int grp = lane >> 2, tI = lane & 3;
    const int wm = (wid >> 2) * 64, wn = (wid & 3) * 32;
    const int bm = blockIdx.y * 128, bn = blockIdx.x * 128;
    const int e = blockIdx.z;
    if (cntp && bm >= cntp[e]) return;
    const int* tix = tix_base + (size_t)e * tix_stride;
    const size_t beoff = (size_t)e * fdim * DDIM;
    const __half* Bg = Gw + beoff;
    const __half* Bu = Uw + beoff;

    const int lr = tid >> 2, lq = tid & 3;
    const uint32_t ds0 = lr * MSTRIDE + lq * 16;
    const uint32_t ds1 = (lr + 64) * MSTRIDE + lq * 16;
    const int tokA0 = tix[bm + lr];
    const int tokA1 = tix[bm + lr + 64];
    const size_t gA0 = (size_t)tokA0 * DDIM + lq * 8;
    const size_t gA1 = (size_t)tokA1 * DDIM + lq * 8;
    const size_t gB0 = (size_t)(bn + lr) * DDIM + lq * 8;
    const size_t gB1 = gB0 + (size_t)64 * DDIM;

    const uint32_t aOff = (lane & 15) * MSTRIDE + (lane >> 4) * 16;
    const uint32_t bOff = (lane & 7) * MSTRIDE + ((lane >> 3) & 1) * 16
                        + (lane >> 4) * 8 * MSTRIDE;

    float accG[4][4][4], accU[4][4][4];
#pragma unroll
    for (int i = 0; i < 4; i++)
#pragma unroll
        for (int j = 0; j < 4; j++)
#pragma unroll
            for (int r = 0; r < 4; r++) { accG[i][j][r] = 0.f; accU[i][j][r] = 0.f; }

    const int NC = DDIM / BK;   // 32

    auto issue = [&](int kc, int buf) {
        const int k0 = kc * BK;
        const uint32_t s = sb + buf * GU_SBUF;
        CP16(s + ds0,             X  + gA0 + k0);
        CP16(s + ds1,             X  + gA1 + k0);
        CP16(s + TILEB + ds0,     Bg + gB0 + k0);
        CP16(s + TILEB + ds1,     Bg + gB1 + k0);
        CP16(s + 2 * TILEB + ds0, Bu + gB0 + k0);
        CP16(s + 2 * TILEB + ds1, Bu + gB1 + k0);
        CP_COMMIT();
    };

    issue(0, 0);
    for (int kc = 0; kc < NC; kc++) {
        const int buf = kc & 1;
        if (kc + 1 < NC) { issue(kc + 1, buf ^ 1); CP_WAIT1(); }
        else             { CP_WAIT0(); }
        __syncthreads();
        const uint32_t s = sb + buf * GU_SBUF;
#pragma unroll
        for (int ks = 0; ks < 2; ks++) {
            uint32_t aF[4][4];
            const uint32_t aBase = s + wm * MSTRIDE + aOff + ks * 32;
#pragma unroll
            for (int tm = 0; tm < 4; tm++)
                LDSM4(aF[tm][0], aF[tm][1], aF[tm][2], aF[tm][3],
                      aBase + tm * 16 * MSTRIDE);
            const uint32_t bgB = s + TILEB + wn * MSTRIDE + bOff + ks * 32;
            const uint32_t buB = s + 2 * TILEB + wn * MSTRIDE + bOff + ks * 32;
#pragma unroll
            for (int tn2 = 0; tn2 < 2; tn2++) {
                uint32_t g[4], u[4];
                LDSM4(g[0], g[1], g[2], g[3], bgB + tn2 * 16 * MSTRIDE);
                LDSM4(u[0], u[1], u[2], u[3], buB + tn2 * 16 * MSTRIDE);
                const int tn = tn2 * 2;
#pragma unroll
                for (int tm = 0; tm < 4; tm++) MMA16(accG[tm][tn],     aF[tm], g[0], g[1]);
#pragma unroll
                for (int tm = 0; tm < 4; tm++) MMA16(accU[tm][tn],     aF[tm], u[0], u[1]);
#pragma unroll
                for (int tm = 0; tm < 4; tm++) MMA16(accG[tm][tn + 1], aF[tm], g[2], g[3]);
#pragma unroll
                for (int tm = 0; tm < 4; tm++) MMA16(accU[tm][tn + 1], aF[tm], u[2], u[3]);
            }
        }
        __syncthreads();
    }

    // epilogue: silu(g)*u*route_weight -> fp16 -> H (scattered)
    const int colbase = hbase + e * fdim + bn + wn;
#pragma unroll
    for (int tm = 0; tm < 4; tm++) {
#pragma unroll
        for (int half = 0; half < 2; half++) {
            const int token = tix[bm + wm + tm * 16 + grp + half * 8];
            const float wgt = scaled ? g_W[token * NEXP + e] : 1.0f;
            const size_t rowoff = (size_t)token * KDOWN;
#pragma unroll
            for (int tn = 0; tn < 4; tn++) {
                float gv0 = accG[tm][tn][half * 2 + 0];
                float gv1 = accG[tm][tn][half * 2 + 1];
                float uv0 = accU[tm][tn][half * 2 + 0];
                float uv1 = accU[tm][tn][half * 2 + 1];
                float h0 = gv0 / (1.f + expf(-gv0)) * uv0 * wgt;
                float h1 = gv1 / (1.f + expf(-gv1)) * uv1 * wgt;
                const int col = colbase + tn * 8 + tI * 2;
                *reinterpret_cast<uint32_t*>(g_H + rowoff + col) =
                    pk_h2(__float2half_rn(h0), __float2half_rn(h1));
            }
        }
    }
}

// ---------------- down fp16 MMA GEMM (single-pass, combine) ----------------------
// tiles per buffer: H, Bd
#define DN_SBUF (2 * TILEB)       // 20480
#define DN_SMEM (2 * DN_SBUF)     // 40960

__global__ __launch_bounds__(256, 2)
void dn_mma(float* __restrict__ out) {
    extern __shared__ __align__(16) char smem[];
    const uint32_t sb = smem_u32(smem);
    const int tid = threadIdx.x;
    const int wid = tid >> 5, lane = tid & 31;
    const int grp = lane >> 2, tI = lane & 3;
    const int wm = (wid >> 2) * 64, wn = (wid & 3) * 32;
    const int bm = blockIdx.y * 128, bn = blockIdx.x * 128;

    const int lr = tid >> 2, lq = tid & 3;
    const uint32_t ds0 = lr * MSTRIDE + lq * 16;
    const uint32_t ds1 = (lr + 64) * MSTRIDE + lq * 16;
    const size_t gA0 = (size_t)(bm + lr) * KDOWN + lq * 8;
    const size_t gA1 = gA0 + (size_t)64 * KDOWN;
    const size_t gB0 = (size_t)(bn + lr) * KDOWN + lq * 8;
    const size_t gB1 = gB0 + (size_t)64 * KDOWN;

    const uint32_t aOff = (lane & 15) * MSTRIDE + (lane >> 4) * 16;
    const uint32_t bOff = (lane & 7) * MSTRIDE + ((lane >> 3) & 1) * 16
                        + (lane >> 4) * 8 * MSTRIDE;

    float acc[4][4][4];
#pragma unroll
    for (int i = 0; i < 4; i++)
#pragma unroll
        for (int j = 0; j < 4; j++)
#pragma unroll
            for (int r = 0; r < 4; r++) acc[i][j][r] = 0.f;

    const int NC = KDOWN / BK;   // 160

    auto issue = [&](int kc, int buf) {
        const int k0 = kc * BK;
        const uint32_t s = sb + buf * DN_SBUF;
        CP16(s + ds0,         g_H  + gA0 + k0);
        CP16(s + ds1,         g_H  + gA1 + k0);
        CP16(s + TILEB + ds0, g_Bd + gB0 + k0);
        CP16(s + TILEB + ds1, g_Bd + gB1 + k0);
        CP_COMMIT();
    };

    issue(0, 0);
    for (int kc = 0; kc < NC; kc++) {
        const int buf = kc & 1;
        if (kc + 1 < NC) { issue(kc + 1, buf ^ 1); CP_WAIT1(); }
        else             { CP_WAIT0(); }
        __syncthreads();
        const uint32_t s = sb + buf * DN_SBUF;
#pragma unroll
        for (int ks = 0; ks < 2; ks++) {
            uint32_t aF[4][4];
            const uint32_t aBase = s + wm * MSTRIDE + aOff + ks * 32;
#pragma unroll
            for (int tm = 0; tm < 4; tm++)
                LDSM4(aF[tm][0], aF[tm][1], aF[tm][2], aF[tm][3],
                      aBase + tm * 16 * MSTRIDE);
            const uint32_t bB = s + TILEB + wn * MSTRIDE + bOff + ks * 32;
#pragma unroll
            for (int tn2 = 0; tn2 < 2; tn2++) {
                uint32_t b[4];
                LDSM4(b[0], b[1], b[2], b[3], bB + tn2 * 16 * MSTRIDE);
                const int tn = tn2 * 2;
#pragma unroll
                for (int tm = 0; tm < 4; tm++) MMA16(acc[tm][tn],     aF[tm], b[0], b[1]);
#pragma unroll
                for (int tm = 0; tm < 4; tm++) MMA16(acc[tm][tn + 1], aF[tm], b[2], b[3]);
            }
        }
        __syncthreads();
    }

#pragma unroll
    for (int tm = 0; tm < 4; tm++) {
#pragma unroll
        for (int half = 0; half < 2; half++) {
            const int token = bm + wm + tm * 16 + grp + half * 8;
#pragma unroll
            for (int tn = 0; tn < 4; tn++) {
                const int col = bn + wn + tn * 8 + tI * 2;
                float2 v = make_float2(acc[tm][tn][half * 2], acc[tm][tn][half * 2 + 1]);
                *reinterpret_cast<float2*>(out + (size_t)token * DDIM + col) = v;
            }
        }
    }
}

// ---------------- launch ----------------------------------------------------------
extern "C" void kernel_launch(void* const* d_in, const int* in_sizes, int n_in,
                              void* d_out, int out_size) {
    const float* x   = (const float*)d_in[0];
    const float* rw  = (const float*)d_in[1];
    const float* wg  = (const float*)d_in[2];
    const float* wu  = (const float*)d_in[3];
    const float* wd  = (const float*)d_in[4];
    const float* wsg = (const float*)d_in[5];
    const float* wsu = (const float*)d_in[6];
    const float* wsd = (const float*)d_in[7];
    float* out = (float*)d_out;

    void *pX, *pBg, *pBu, *pBsg, *pBsu, *pBd, *pIdx, *pIdxI, *pCntp;
    cudaGetSymbolAddress(&pX, g_X);
    cudaGetSymbolAddress(&pBg, g_Bg);   cudaGetSymbolAddress(&pBu, g_Bu);
    cudaGetSymbolAddress(&pBsg, g_Bsg); cudaGetSymbolAddress(&pBsu, g_Bsu);
    cudaGetSymbolAddress(&pBd, g_Bd);
    cudaGetSymbolAddress(&pIdx, g_idx); cudaGetSymbolAddress(&pIdxI, g_idxI);
    cudaGetSymbolAddress(&pCntp, g_cntp);

    cudaFuncSetAttribute(gu_mma, cudaFuncAttributeMaxDynamicSharedMemorySize, GU_SMEM);
    cudaFuncSetAttribute(dn_mma, cudaFuncAttributeMaxDynamicSharedMemorySize, DN_SMEM);

    init_lists<<<16, 256>>>();
    router_kernel<<<T_TOK / 4, 128>>>(x, rw);
    pad_idx<<<NEXP, 128>>>();
    cvt<<<T_TOK * DDIM / 1024, 256>>>(x, (__half*)pX);
    zeroH<<<(T_TOK * (size_t)KDOWN) / (256 * 8), 256>>>();
    dim3 tb(32, 8);
    prepA<<<dim3(16, 32, 16), tb>>>(wg, wu, (__half*)pBg, (__half*)pBu);
    prepB<<<dim3(32, 32, 11), tb>>>(wsg, wsu, wd, wsd,
        (__half*)pBsg, (__half*)pBsu, (__half*)pBd);
    // shared expert gate+up (dense) -> H[:, 4096:5120]
    gu_mma<<<dim3(FSDIM / 128, T_TOK / 128, 1), 256, GU_SMEM>>>(
        (const __half*)pX,
        (const __half*)pBsg, (const __half*)pBsu,
        (const int*)pIdxI, 0, nullptr,
        FSDIM, NEXP * FDIM, 0);
    // routed experts gate+up (gathered) -> H[:, 0:4096]
    gu_mma<<<dim3(FDIM / 128, T_TOK / 128, NEXP), 256, GU_SMEM>>>(
        (const __half*)pX,
        (const __half*)pBg, (const __half*)pBu,
        (const int*)pIdx, IDXSTR, (const int*)pCntp,
        FDIM, 0, 1);
    // down + weighted combine + shared add
    dn_mma<<<dim3(DDIM / 128, T_TOK / 128), 256, DN_SMEM>>>(out);
}

// round 9
// speedup vs baseline: 6.3035x; 1.2155x over previous
#include <cuda_runtime.h>
#include <cuda_fp16.h>
#include <math.h>
#include <stdint.h>

#define T_TOK 4096
#define DDIM  1024
#define NEXP  8
#define FDIM  512
#define FSDIM 1024
#define KDOWN 5120
#define TOPK  6

#define BK 64
#define MSTRIDE 144                // 128 data + 16 pad: 16B-aligned, ldmatrix conflict-free
#define TILEB (128 * MSTRIDE)      // 18432 bytes per 128-row tile
#define IDXSTR 4096

// ---------------- scratch ----------------------------------------------------
__device__ float g_W[T_TOK * NEXP];
__device__ int   g_idx[NEXP * IDXSTR];
__device__ int   g_cnt[NEXP];
__device__ __half g_X[T_TOK * DDIM];
__device__ __half g_Bg[NEXP * FDIM * DDIM];      // fp16 weights, K-major [n][k]
__device__ __half g_Bu[NEXP * FDIM * DDIM];
__device__ __half g_Bsg[FSDIM * DDIM];
__device__ __half g_Bsu[FSDIM * DDIM];
__device__ __half g_Bd[DDIM * KDOWN];            // [n=1024][k=5120]
__device__ __half g_H[(size_t)T_TOK * KDOWN];

// ---------------- helpers ----------------------------------------------------
__device__ __forceinline__ uint32_t smem_u32(const void* p) {
    uint32_t a;
    asm("{ .reg .u64 t; cvta.to.shared.u64 t, %1; cvt.u32.u64 %0, t; }"
        : "=r"(a) : "l"(p));
    return a;
}

#define CP16(dst, src) \
    asm volatile("cp.async.cg.shared.global [%0], [%1], 16;" :: "r"(dst), "l"(src) : "memory")
#define CP_COMMIT() asm volatile("cp.async.commit_group;" ::: "memory")
#define CP_WAIT1()  asm volatile("cp.async.wait_group 1;" ::: "memory")
#define CP_WAIT0()  asm volatile("cp.async.wait_group 0;" ::: "memory")

#define LDSM4(r0, r1, r2, r3, a) \
    asm volatile("ldmatrix.sync.aligned.m8n8.x4.shared.b16 {%0,%1,%2,%3}, [%4];" \
        : "=r"(r0), "=r"(r1), "=r"(r2), "=r"(r3) : "r"(a))

#define MMA16(d, a, b0, b1) \
    asm volatile( \
        "mma.sync.aligned.m16n8k16.row.col.f32.f16.f16.f32 " \
        "{%0,%1,%2,%3},{%4,%5,%6,%7},{%8,%9},{%0,%1,%2,%3};" \
        : "+f"((d)[0]), "+f"((d)[1]), "+f"((d)[2]), "+f"((d)[3]) \
        : "r"((a)[0]), "r"((a)[1]), "r"((a)[2]), "r"((a)[3]), "r"(b0), "r"(b1))

__device__ __forceinline__ uint32_t pk_h2(__half a, __half b) {
    __half2 t = __halves2half2(a, b);
    return *reinterpret_cast<uint32_t*>(&t);
}

// ---------------- zero H + reset expert counters --------------------------------
__global__ void zeroH() {
    size_t i = ((size_t)blockIdx.x * 256 + threadIdx.x) * 8;
    *reinterpret_cast<uint4*>(g_H + i) = make_uint4(0, 0, 0, 0);
    if (blockIdx.x == 0 && threadIdx.x < NEXP) g_cnt[threadIdx.x] = 0;
}

// ---------------- router + per-expert token lists --------------------------------
__global__ void router_kernel(const float* __restrict__ x,
                              const float* __restrict__ rw) {
    int gw = (blockIdx.x * blockDim.x + threadIdx.x) >> 5;
    int lane = threadIdx.x & 31;
    if (gw >= T_TOK) return;
    const float* xr = x + (size_t)gw * DDIM;
    float acc[NEXP];
#pragma unroll
    for (int e = 0; e < NEXP; e++) acc[e] = 0.f;
    for (int d = lane; d < DDIM; d += 32) {
        float xv = xr[d];
        const float4* r4 = reinterpret_cast<const float4*>(rw + (size_t)d * NEXP);
        float4 r0 = r4[0], r1 = r4[1];
        acc[0] = fmaf(xv, r0.x, acc[0]); acc[1] = fmaf(xv, r0.y, acc[1]);
        acc[2] = fmaf(xv, r0.z, acc[2]); acc[3] = fmaf(xv, r0.w, acc[3]);
        acc[4] = fmaf(xv, r1.x, acc[4]); acc[5] = fmaf(xv, r1.y, acc[5]);
        acc[6] = fmaf(xv, r1.z, acc[6]); acc[7] = fmaf(xv, r1.w, acc[7]);
    }
#pragma unroll
    for (int off = 16; off > 0; off >>= 1)
#pragma unroll
        for (int e = 0; e < NEXP; e++)
            acc[e] += __shfl_xor_sync(0xffffffffu, acc[e], off);
    if (lane == 0) {
        float m = acc[0];
#pragma unroll
        for (int e = 1; e < NEXP; e++) m = fmaxf(m, acc[e]);
        float p[NEXP], s = 0.f;
#pragma unroll
        for (int e = 0; e < NEXP; e++) { p[e] = expf(acc[e] - m); s += p[e]; }
        float inv = 1.f / s;
#pragma unroll
        for (int e = 0; e < NEXP; e++) p[e] *= inv;
#pragma unroll
        for (int e = 0; e < NEXP; e++) {
            int rank = 0;
#pragma unroll
            for (int e2 = 0; e2 < NEXP; e2++)
                rank += (p[e2] > p[e] || (p[e2] == p[e] && e2 < e)) ? 1 : 0;
            bool sel = (rank < TOPK);
            g_W[gw * NEXP + e] = sel ? p[e] : 0.f;
            if (sel) {
                int pos = atomicAdd(&g_cnt[e], 1);
                g_idx[e * IDXSTR + pos] = gw;
            }
        }
    }
}

// ---------------- conversions -----------------------------------------------------
__global__ void cvt(const float* __restrict__ src, __half* __restrict__ dst) {
    int i = (blockIdx.x * 256 + threadIdx.x) * 4;
    float4 v = *reinterpret_cast<const float4*>(src + i);
    uint2 p;
    p.x = pk_h2(__float2half_rn(v.x), __float2half_rn(v.y));
    p.y = pk_h2(__float2half_rn(v.z), __float2half_rn(v.w));
    *reinterpret_cast<uint2*>(dst + i) = p;
}

__device__ __forceinline__ void tpose_body(
    const float* __restrict__ src, __half* __restrict__ dst,
    int C, long long zs, long long zd, int rs) {
    __shared__ float t[32][33];
    int c0 = blockIdx.x * 32, r0 = blockIdx.y * 32;
    int tx = threadIdx.x, ty = threadIdx.y;
#pragma unroll
    for (int k = 0; k < 32; k += 8)
        t[ty + k][tx] = src[zs + (long long)(r0 + ty + k) * C + c0 + tx];
    __syncthreads();
#pragma unroll
    for (int k = 0; k < 32; k += 8) {
        float v = t[tx][ty + k];
        int n = c0 + ty + k, r = r0 + tx;
        dst[zd + (long long)n * rs + r] = __float2half_rn(v);
    }
}

__global__ void prepA(const float* __restrict__ wg, const float* __restrict__ wu,
                      __half* bg, __half* bu) {
    int z = blockIdx.z;
    if (z < 8)
        tpose_body(wg, bg, FDIM, (long long)z * DDIM * FDIM, (long long)z * FDIM * DDIM, DDIM);
    else
        tpose_body(wu, bu, FDIM, (long long)(z - 8) * DDIM * FDIM, (long long)(z - 8) * FDIM * DDIM, DDIM);
}

__global__ void prepB(const float* __restrict__ wsg, const float* __restrict__ wsu,
                      const float* __restrict__ wd,  const float* __restrict__ wsd,
                      __half* bsg, __half* bsu, __half* bd) {
    int z = blockIdx.z;
    if (z == 0)      tpose_body(wsg, bsg, FSDIM, 0, 0, DDIM);
    else if (z == 1) tpose_body(wsu, bsu, FSDIM, 0, 0, DDIM);
    else if (z <= 9) {
        if (blockIdx.y >= 16) return;
        int e = z - 2;
        tpose_body(wd, bd, DDIM, (long long)e * FDIM * DDIM, (long long)e * FDIM, KDOWN);
    } else
        tpose_body(wsd, bd, DDIM, 0, (long long)NEXP * FDIM, KDOWN);
}

// ---------------- merged gate+up fp16 MMA GEMM (z=0..7 routed, z=8 shared) -------
// tiles per buffer: A, Bg, Bu
#define GU_SBUF (3 * TILEB)       // 55296
#define GU_SMEM (2 * GU_SBUF)     // 110592

__global__ __launch_bounds__(256, 1)
void gu_mma(const __half* __restrict__ X,
            const __half* __restrict__ Gw,  const __half* __restrict__ Uw,
            const __half* __restrict__ Gsw, const __half* __restrict__ Usw) {
    const int e = blockIdx.z;
    const int bm = blockIdx.y * 128, bn = blockIdx.x * 128;

    const __half *Bg, *Bu;
    const int* tix = nullptr;
    int cnt = 0, fdim, colExp, scaled;
    if (e < NEXP) {
        cnt = g_cnt[e];
        if (bm >= ((cnt + 127) & ~127)) return;
        if (bn >= FDIM) return;
        tix = g_idx + (size_t)e * IDXSTR;
        Bg = Gw + (size_t)e * FDIM * DDIM;
        Bu = Uw + (size_t)e * FDIM * DDIM;
        fdim = FDIM; colExp = e * FDIM; scaled = 1;
    } else {
        Bg = Gsw; Bu = Usw;
        fdim = FSDIM; colExp = NEXP * FDIM; scaled = 0;
    }

    extern __shared__ __align__(16) char smem[];
    const uint32_t sb = smem_u32(smem);
    const int tid = threadIdx.x;
    const int wid = tid >> 5, lane = tid & 31;
    const int grp = lane >> 2, tI = lane & 3;
    const int wm = (wid >> 2) * 64, wn = (wid & 3) * 32;

    // cp.async slots: 4 passes per tile; row = r0 + 32p, q = tid & 7
    const int r0 = tid >> 3, q = tid & 7;
    uint32_t ds[4];
    size_t gA[4], gB[4];
#pragma unroll
    for (int p = 0; p < 4; p++) {
        const int row = r0 + 32 * p;
        ds[p] = row * MSTRIDE + q * 16;
        const int tokA = tix ? tix[min(bm + row, cnt - 1)] : (bm + row);
        gA[p] = (size_t)tokA * DDIM + q * 8;
        gB[p] = (size_t)(bn + row) * DDIM + q * 8;
    }

    const uint32_t aOff = (lane & 15) * MSTRIDE + (lane >> 4) * 16;
    const uint32_t bOff = (lane & 7) * MSTRIDE + ((lane >> 3) & 1) * 16
                        + (lane >> 4) * 8 * MSTRIDE;

    float accG[4][4][4], accU[4][4][4];
#pragma unroll
    for (int i = 0; i < 4; i++)
#pragma unroll
        for (int j = 0; j < 4; j++)
#pragma unroll
            for (int r = 0; r < 4; r++) { accG[i][j][r] = 0.f; accU[i][j][r] = 0.f; }

    const int NC = DDIM / BK;   // 16

    auto issue = [&](int kc, int buf) {
        const int k0 = kc * BK;
        const uint32_t s = sb + buf * GU_SBUF;
#pragma unroll
        for (int p = 0; p < 4; p++) {
            CP16(s + ds[p],             X  + gA[p] + k0);
            CP16(s + TILEB + ds[p],     Bg + gB[p] + k0);
            CP16(s + 2 * TILEB + ds[p], Bu + gB[p] + k0);
        }
        CP_COMMIT();
    };

    issue(0, 0);
    for (int kc = 0; kc < NC; kc++) {
        const int buf = kc & 1;
        if (kc + 1 < NC) { issue(kc + 1, buf ^ 1); CP_WAIT1(); }
        else             { CP_WAIT0(); }
        __syncthreads();
        const uint32_t s = sb + buf * GU_SBUF;
#pragma unroll
        for (int ks = 0; ks < 4; ks++) {
            uint32_t aF[4][4];
            const uint32_t aBase = s + wm * MSTRIDE + aOff + ks * 32;
#pragma unroll
            for (int tm = 0; tm < 4; tm++)
                LDSM4(aF[tm][0], aF[tm][1], aF[tm][2], aF[tm][3],
                      aBase + tm * 16 * MSTRIDE);
            const uint32_t bgB = s + TILEB + wn * MSTRIDE + bOff + ks * 32;
            const uint32_t buB = s + 2 * TILEB + wn * MSTRIDE + bOff + ks * 32;
#pragma unroll
            for (int tn2 = 0; tn2 < 2; tn2++) {
                uint32_t g[4], u[4];
                LDSM4(g[0], g[1], g[2], g[3], bgB + tn2 * 16 * MSTRIDE);
                LDSM4(u[0], u[1], u[2], u[3], buB + tn2 * 16 * MSTRIDE);
                const int tn = tn2 * 2;
#pragma unroll
                for (int tm = 0; tm < 4; tm++) MMA16(accG[tm][tn],     aF[tm], g[0], g[1]);
#pragma unroll
                for (int tm = 0; tm < 4; tm++) MMA16(accU[tm][tn],     aF[tm], u[0], u[1]);
#pragma unroll
                for (int tm = 0; tm < 4; tm++) MMA16(accG[tm][tn + 1], aF[tm], g[2], g[3]);
#pragma unroll
                for (int tm = 0; tm < 4; tm++) MMA16(accU[tm][tn + 1], aF[tm], u[2], u[3]);
            }
        }
        __syncthreads();
    }

    // epilogue: silu(g)*u*route_weight -> fp16 -> H (scattered)
    const int colbase = colExp + bn + wn;
#pragma unroll
    for (int tm = 0; tm < 4; tm++) {
#pragma unroll
        for (int half = 0; half < 2; half++) {
            const int i = bm + wm + tm * 16 + grp + half * 8;
            const int token = tix ? tix[min(i, cnt - 1)] : i;
            const float wgt = scaled ? g_W[token * NEXP + e] : 1.0f;
            const size_t rowoff = (size_t)token * KDOWN;
#pragma unroll
            for (int tn = 0; tn < 4; tn++) {
                float gv0 = accG[tm][tn][half * 2 + 0];
                float gv1 = accG[tm][tn][half * 2 + 1];
                float uv0 = accU[tm][tn][half * 2 + 0];
                float uv1 = accU[tm][tn][half * 2 + 1];
                float h0 = gv0 / (1.f + expf(-gv0)) * uv0 * wgt;
                float h1 = gv1 / (1.f + expf(-gv1)) * uv1 * wgt;
                const int col = colbase + tn * 8 + tI * 2;
                *reinterpret_cast<uint32_t*>(g_H + rowoff + col) =
                    pk_h2(__float2half_rn(h0), __float2half_rn(h1));
            }
        }
    }
}

// ---------------- down fp16 MMA GEMM (combine) --------------------------------------
// tiles per buffer: H, Bd
#define DN_SBUF (2 * TILEB)       // 36864
#define DN_SMEM (2 * DN_SBUF)     // 73728

__global__ __launch_bounds__(256, 2)
void dn_mma(float* __restrict__ out) {
    extern __shared__ __align__(16) char smem[];
    const uint32_t sb = smem_u32(smem);
    const int tid = threadIdx.x;
    const int wid = tid >> 5, lane = tid & 31;
    const int grp = lane >> 2, tI = lane & 3;
    const int wm = (wid >> 2) * 64, wn = (wid & 3) * 32;
    const int bm = blockIdx.y * 128, bn = blockIdx.x * 128;

    const int r0 = tid >> 3, q = tid & 7;
    uint32_t ds[4];
    size_t gA[4], gB[4];
#pragma unroll
    for (int p = 0; p < 4; p++) {
        const int row = r0 + 32 * p;
        ds[p] = row * MSTRIDE + q * 16;
        gA[p] = (size_t)(bm + row) * KDOWN + q * 8;
        gB[p] = (size_t)(bn + row) * KDOWN + q * 8;
    }

    const uint32_t aOff = (lane & 15) * MSTRIDE + (lane >> 4) * 16;
    const uint32_t bOff = (lane & 7) * MSTRIDE + ((lane >> 3) & 1) * 16
                        + (lane >> 4) * 8 * MSTRIDE;

    float acc[4][4][4];
#pragma unroll
    for (int i = 0; i < 4; i++)
#pragma unroll
        for (int j = 0; j < 4; j++)
#pragma unroll
            for (int r = 0; r < 4; r++) acc[i][j][r] = 0.f;

    const int NC = KDOWN / BK;   // 80

    auto issue = [&](int kc, int buf) {
        const int k0 = kc * BK;
        const uint32_t s = sb + buf * DN_SBUF;
#pragma unroll
        for (int p = 0; p < 4; p++) {
            CP16(s + ds[p],         g_H  + gA[p] + k0);
            CP16(s + TILEB + ds[p], g_Bd + gB[p] + k0);
        }
        CP_COMMIT();
    };

    issue(0, 0);
    for (int kc = 0; kc < NC; kc++) {
        const int buf = kc & 1;
        if (kc + 1 < NC) { issue(kc + 1, buf ^ 1); CP_WAIT1(); }
        else             { CP_WAIT0(); }
        __syncthreads();
        const uint32_t s = sb + buf * DN_SBUF;
#pragma unroll
        for (int ks = 0; ks < 4; ks++) {
            uint32_t aF[4][4];
            const uint32_t aBase = s + wm * MSTRIDE + aOff + ks * 32;
#pragma unroll
            for (int tm = 0; tm < 4; tm++)
                LDSM4(aF[tm][0], aF[tm][1], aF[tm][2], aF[tm][3],
                      aBase + tm * 16 * MSTRIDE);
            const uint32_t bB = s + TILEB + wn * MSTRIDE + bOff + ks * 32;
#pragma unroll
            for (int tn2 = 0; tn2 < 2; tn2++) {
                uint32_t b[4];
                LDSM4(b[0], b[1], b[2], b[3], bB + tn2 * 16 * MSTRIDE);
                const int tn = tn2 * 2;
#pragma unroll
                for (int tm = 0; tm < 4; tm++) MMA16(acc[tm][tn],     aF[tm], b[0], b[1]);
#pragma unroll
                for (int tm = 0; tm < 4; tm++) MMA16(acc[tm][tn + 1], aF[tm], b[2], b[3]);
            }
        }
        __syncthreads();
    }

#pragma unroll
    for (int tm = 0; tm < 4; tm++) {
#pragma unroll
        for (int half = 0; half < 2; half++) {
            const int token = bm + wm + tm * 16 + grp + half * 8;
#pragma unroll
            for (int tn = 0; tn < 4; tn++) {
                const int col = bn + wn + tn * 8 + tI * 2;
                float2 v = make_float2(acc[tm][tn][half * 2], acc[tm][tn][half * 2 + 1]);
                *reinterpret_cast<float2*>(out + (size_t)token * DDIM + col) = v;
            }
        }
    }
}

// ---------------- launch ------------------------------------------------------------
extern "C" void kernel_launch(void* const* d_in, const int* in_sizes, int n_in,
                              void* d_out, int out_size) {
    const float* x   = (const float*)d_in[0];
    const float* rw  = (const float*)d_in[1];
    const float* wg  = (const float*)d_in[2];
    const float* wu  = (const float*)d_in[3];
    const float* wd  = (const float*)d_in[4];
    const float* wsg = (const float*)d_in[5];
    const float* wsu = (const float*)d_in[6];
    const float* wsd = (const float*)d_in[7];
    float* out = (float*)d_out;

    void *pX, *pBg, *pBu, *pBsg, *pBsu, *pBd;
    cudaGetSymbolAddress(&pX, g_X);
    cudaGetSymbolAddress(&pBg, g_Bg);   cudaGetSymbolAddress(&pBu, g_Bu);
    cudaGetSymbolAddress(&pBsg, g_Bsg); cudaGetSymbolAddress(&pBsu, g_Bsu);
    cudaGetSymbolAddress(&pBd, g_Bd);

    cudaFuncSetAttribute(gu_mma, cudaFuncAttributeMaxDynamicSharedMemorySize, GU_SMEM);
    cudaFuncSetAttribute(dn_mma, cudaFuncAttributeMaxDynamicSharedMemorySize, DN_SMEM);

    // 1: zero H + reset counters
    zeroH<<<(T_TOK * (size_t)KDOWN) / (256 * 8), 256>>>();
    // 2: router + compacted expert token lists
    router_kernel<<<T_TOK / 4, 128>>>(x, rw);
    // 3: activation fp16
    cvt<<<T_TOK * DDIM / 1024, 256>>>(x, (__half*)pX);
    // 4-5: weight transpose/convert
    dim3 tb(32, 8);
    prepA<<<dim3(16, 32, 16), tb>>>(wg, wu, (__half*)pBg, (__half*)pBu);
    prepB<<<dim3(32, 32, 11), tb>>>(wsg, wsu, wd, wsd,
        (__half*)pBsg, (__half*)pBsu, (__half*)pBd);
    // 6: merged gate+up (routed z=0..7 gathered, shared z=8 dense)
    gu_mma<<<dim3(FSDIM / 128, T_TOK / 128, NEXP + 1), 256, GU_SMEM>>>(
        (const __half*)pX,
        (const __half*)pBg,  (const __half*)pBu,
        (const __half*)pBsg, (const __half*)pBsu);
    // 7: down + weighted combine + shared add
    dn_mma<<<dim3(DDIM / 128, T_TOK / 128), 256, DN_SMEM>>>(out);
}

// round 11
// speedup vs baseline: 6.3339x; 1.0048x over previous
#include <cuda_runtime.h>
#include <cuda_fp16.h>
#include <math.h>
#include <stdint.h>

#define T_TOK 4096
#define DDIM  1024
#define NEXP  8
#define FDIM  512
#define FSDIM 1024
#define KDOWN 5120
#define TOPK  6

#define BK 64
#define MSTRIDE 144                // 128 data + 16 pad: 16B-aligned, ldmatrix conflict-free
#define TILEB (128 * MSTRIDE)      // 18432 bytes per 128-row tile
#define IDXSTR 4096

// ---------------- scratch ----------------------------------------------------
__device__ float g_W[T_TOK * NEXP];
__device__ int   g_idx[NEXP * IDXSTR];    // selected tokens per expert
__device__ int   g_idxz[NEXP * IDXSTR];   // UNselected tokens per expert
__device__ int   g_cnt[NEXP];
__device__ int   g_cntz[NEXP];
__device__ __half g_X[T_TOK * DDIM];
__device__ __half g_Bg[NEXP * FDIM * DDIM];      // fp16 weights, K-major [n][k]
__device__ __half g_Bu[NEXP * FDIM * DDIM];
__device__ __half g_Bsg[FSDIM * DDIM];
__device__ __half g_Bsu[FSDIM * DDIM];
__device__ __half g_Bd[DDIM * KDOWN];            // [n=1024][k=5120]
__device__ __half g_H[(size_t)T_TOK * KDOWN];

// ---------------- helpers ----------------------------------------------------
__device__ __forceinline__ uint32_t smem_u32(const void* p) {
    uint32_t a;
    asm("{ .reg .u64 t; cvta.to.shared.u64 t, %1; cvt.u32.u64 %0, t; }"
        : "=r"(a) : "l"(p));
    return a;
}

#define CP16(dst, src) \
    asm volatile("cp.async.cg.shared.global [%0], [%1], 16;" :: "r"(dst), "l"(src) : "memory")
#define CP_COMMIT() asm volatile("cp.async.commit_group;" ::: "memory")
#define CP_WAIT1()  asm volatile("cp.async.wait_group 1;" ::: "memory")
#define CP_WAIT0()  asm volatile("cp.async.wait_group 0;" ::: "memory")

#define LDSM4(r0, r1, r2, r3, a) \
    asm volatile("ldmatrix.sync.aligned.m8n8.x4.shared.b16 {%0,%1,%2,%3}, [%4];" \
        : "=r"(r0), "=r"(r1), "=r"(r2), "=r"(r3) : "r"(a))

#define MMA16(d, a, b0, b1) \
    asm volatile( \
        "mma.sync.aligned.m16n8k16.row.col.f32.f16.f16.f32 " \
        "{%0,%1,%2,%3},{%4,%5,%6,%7},{%8,%9},{%0,%1,%2,%3};" \
        : "+f"((d)[0]), "+f"((d)[1]), "+f"((d)[2]), "+f"((d)[3]) \
        : "r"((a)[0]), "r"((a)[1]), "r"((a)[2]), "r"((a)[3]), "r"(b0), "r"(b1))

__device__ __forceinline__ uint32_t pk_h2(__half a, __half b) {
    __half2 t = __halves2half2(a, b);
    return *reinterpret_cast<uint32_t*>(&t);
}

// ---------------- counter reset ------------------------------------------------
__global__ void zcnt() {
    if (threadIdx.x < NEXP) { g_cnt[threadIdx.x] = 0; g_cntz[threadIdx.x] = 0; }
}

// ---------------- fused router: scores + topk lists + complement + X fp16 -------
__global__ void router_kernel(const float* __restrict__ x,
                              const float* __restrict__ rw,
                              __half* __restrict__ xh) {
    int gw = (blockIdx.x * blockDim.x + threadIdx.x) >> 5;
    int lane = threadIdx.x & 31;
    if (gw >= T_TOK) return;
    const float* xr = x + (size_t)gw * DDIM;
    __half* xo = xh + (size_t)gw * DDIM;
    float acc[NEXP];
#pragma unroll
    for (int e = 0; e < NEXP; e++) acc[e] = 0.f;
    for (int d = lane; d < DDIM; d += 32) {
        float xv = xr[d];
        xo[d] = __float2half_rn(xv);               // fused fp16 conversion
        const float4* r4 = reinterpret_cast<const float4*>(rw + (size_t)d * NEXP);
        float4 r0 = r4[0], r1 = r4[1];
        acc[0] = fmaf(xv, r0.x, acc[0]); acc[1] = fmaf(xv, r0.y, acc[1]);
        acc[2] = fmaf(xv, r0.z, acc[2]); acc[3] = fmaf(xv, r0.w, acc[3]);
        acc[4] = fmaf(xv, r1.x, acc[4]); acc[5] = fmaf(xv, r1.y, acc[5]);
        acc[6] = fmaf(xv, r1.z, acc[6]); acc[7] = fmaf(xv, r1.w, acc[7]);
    }
#pragma unroll
    for (int off = 16; off > 0; off >>= 1)
#pragma unroll
        for (int e = 0; e < NEXP; e++)
            acc[e] += __shfl_xor_sync(0xffffffffu, acc[e], off);
    if (lane == 0) {
        float m = acc[0];
#pragma unroll
        for (int e = 1; e < NEXP; e++) m = fmaxf(m, acc[e]);
        float p[NEXP], s = 0.f;
#pragma unroll
        for (int e = 0; e < NEXP; e++) { p[e] = expf(acc[e] - m); s += p[e]; }
        float inv = 1.f / s;
#pragma unroll
        for (int e = 0; e < NEXP; e++) p[e] *= inv;
#pragma unroll
        for (int e = 0; e < NEXP; e++) {
            int rank = 0;
#pragma unroll
            for (int e2 = 0; e2 < NEXP; e2++)
                rank += (p[e2] > p[e] || (p[e2] == p[e] && e2 < e)) ? 1 : 0;
            bool sel = (rank < TOPK);
            g_W[gw * NEXP + e] = sel ? p[e] : 0.f;
            if (sel) {
                int pos = atomicAdd(&g_cnt[e], 1);
                g_idx[e * IDXSTR + pos] = gw;
            } else {
                int pos = atomicAdd(&g_cntz[e], 1);
                g_idxz[e * IDXSTR + pos] = gw;
            }
        }
    }
}

// ---------------- zero only unselected (token, expert) H slots -------------------
__global__ void zeroSel() {
    const int e = blockIdx.x;
    const int nz = g_cntz[e];
    const int sub = threadIdx.x >> 6;        // 4 rows per block-iter
    const int ln  = threadIdx.x & 63;        // 64 lanes x 8 halves = 512 cols
    for (int i = blockIdx.y * 4 + sub; i < nz; i += 32 * 4) {
        const int tok = g_idxz[e * IDXSTR + i];
        *reinterpret_cast<uint4*>(g_H + (size_t)tok * KDOWN + e * FDIM + ln * 8) =
            make_uint4(0, 0, 0, 0);
    }
}

// ---------------- weight transpose/convert ---------------------------------------
__device__ __forceinline__ void tpose_body(
    const float* __restrict__ src, __half* __restrict__ dst,
    int C, long long zs, long long zd, int rs) {
    __shared__ float t[32][33];
    int c0 = blockIdx.x * 32, r0 = blockIdx.y * 32;
    int tx = threadIdx.x, ty = threadIdx.y;
#pragma unroll
    for (int k = 0; k < 32; k += 8)
        t[ty + k][tx] = src[zs + (long long)(r0 + ty + k) * C + c0 + tx];
    __syncthreads();
#pragma unroll
    for (int k = 0; k < 32; k += 8) {
        float v = t[tx][ty + k];
        int n = c0 + ty + k, r = r0 + tx;
        dst[zd + (long long)n * rs + r] = __float2half_rn(v);
    }
}

__global__ void prepA(const float* __restrict__ wg, const float* __restrict__ wu,
                      __half* bg, __half* bu) {
    int z = blockIdx.z;
    if (z < 8)
        tpose_body(wg, bg, FDIM, (long long)z * DDIM * FDIM, (long long)z * FDIM * DDIM, DDIM);
    else
        tpose_body(wu, bu, FDIM, (long long)(z - 8) * DDIM * FDIM, (long long)(z - 8) * FDIM * DDIM, DDIM);
}

__global__ void prepB(const float* __restrict__ wsg, const float* __restrict__ wsu,
                      const float* __restrict__ wd,  const float* __restrict__ wsd,
                      __half* bsg, __half* bsu, __half* bd) {
    int z = blockIdx.z;
    if (z == 0)      tpose_body(wsg, bsg, FSDIM, 0, 0, DDIM);
    else if (z == 1) tpose_body(wsu, bsu, FSDIM, 0, 0, DDIM);
    else if (z <= 9) {
        if (blockIdx.y >= 16) return;
        int e = z - 2;
        tpose_body(wd, bd, DDIM, (long long)e * FDIM * DDIM, (long long)e * FDIM, KDOWN);
    } else
        tpose_body(wsd, bd, DDIM, 0, (long long)NEXP * FDIM, KDOWN);
}

// ---------------- merged gate+up fp16 MMA GEMM (z=0..7 routed, z=8 shared) -------
#define GU_SBUF (3 * TILEB)       // 55296
#define GU_SMEM (2 * GU_SBUF)     // 110592

__global__ __launch_bounds__(256, 1)
void gu_mma(const __half* __restrict__ X,
            const __half* __restrict__ Gw,  const __half* __restrict__ Uw,
            const __half* __restrict__ Gsw, const __half* __restrict__ Usw) {
    const int e = blockIdx.z;
    const int bm = blockIdx.y * 128, bn = blockIdx.x * 128;

    const __half *Bg, *Bu;
    const int* tix = nullptr;
    int cnt = 0, colExp, scaled;
    if (e < NEXP) {
        cnt = g_cnt[e];
        if (bm >= ((cnt + 127) & ~127)) return;
        if (bn >= FDIM) return;
        tix = g_idx + (size_t)e * IDXSTR;
        Bg = Gw + (size_t)e * FDIM * DDIM;
        Bu = Uw + (size_t)e * FDIM * DDIM;
        colExp = e * FDIM; scaled = 1;
    } else {
        Bg = Gsw; Bu = Usw;
        colExp = NEXP * FDIM; scaled = 0;
    }

    extern __shared__ __align__(16) char smem[];
    const uint32_t sb = smem_u32(smem);
    const int tid = threadIdx.x;
    const int wid = tid >> 5, lane = tid & 31;
    const int grp = lane >> 2, tI = lane & 3;
    const int wm = (wid >> 2) * 64, wn = (wid & 3) * 32;

    const int r0 = tid >> 3, q = tid & 7;
    uint32_t ds[4];
    size_t gA[4], gB[4];
#pragma unroll
    for (int p = 0; p < 4; p++) {
        const int row = r0 + 32 * p;
        ds[p] = row * MSTRIDE + q * 16;
        const int tokA = tix ? tix[min(bm + row, cnt - 1)] : (bm + row);
        gA[p] = (size_t)tokA * DDIM + q * 8;
        gB[p] = (size_t)(bn + row) * DDIM + q * 8;
    }

    const uint32_t aOff = (lane & 15) * MSTRIDE + (lane >> 4) * 16;
    const uint32_t bOff = (lane & 7) * MSTRIDE + ((lane >> 3) & 1) * 16
                        + (lane >> 4) * 8 * MSTRIDE;

    float accG[4][4][4], accU[4][4][4];
#pragma unroll
    for (int i = 0; i < 4; i++)
#pragma unroll
        for (int j = 0; j < 4; j++)
#pragma unroll
            for (int r = 0; r < 4; r++) { accG[i][j][r] = 0.f; accU[i][j][r] = 0.f; }

    const int NC = DDIM / BK;   // 16

    auto issue = [&](int kc, int buf) {
        const int k0 = kc * BK;
        const uint32_t s = sb + buf * GU_SBUF;
#pragma unroll
        for (int p = 0; p < 4; p++) {
            CP16(s + ds[p],             X  + gA[p] + k0);
            CP16(s + TILEB + ds[p],     Bg + gB[p] + k0);
            CP16(s + 2 * TILEB + ds[p], Bu + gB[p] + k0);
        }
        CP_COMMIT();
    };

    issue(0, 0);
    for (int kc = 0; kc < NC; kc++) {
        const int buf = kc & 1;
        if (kc + 1 < NC) { issue(kc + 1, buf ^ 1); CP_WAIT1(); }
        else             { CP_WAIT0(); }
        __syncthreads();
        const uint32_t s = sb + buf * GU_SBUF;
#pragma unroll
        for (int ks = 0; ks < 4; ks++) {
            uint32_t aF[4][4];
            const uint32_t aBase = s + wm * MSTRIDE + aOff + ks * 32;
#pragma unroll
            for (int tm = 0; tm < 4; tm++)
                LDSM4(aF[tm][0], aF[tm][1], aF[tm][2], aF[tm][3],
                      aBase + tm * 16 * MSTRIDE);
            const uint32_t bgB = s + TILEB + wn * MSTRIDE + bOff + ks * 32;
            const uint32_t buB = s + 2 * TILEB + wn * MSTRIDE + bOff + ks * 32;
#pragma unroll
            for (int tn2 = 0; tn2 < 2; tn2++) {
                uint32_t g[4], u[4];
                LDSM4(g[0], g[1], g[2], g[3], bgB + tn2 * 16 * MSTRIDE);
                LDSM4(u[0], u[1], u[2], u[3], buB + tn2 * 16 * MSTRIDE);
                const int tn = tn2 * 2;
#pragma unroll
                for (int tm = 0; tm < 4; tm++) MMA16(accG[tm][tn],     aF[tm], g[0], g[1]);
#pragma unroll
                for (int tm = 0; tm < 4; tm++) MMA16(accU[tm][tn],     aF[tm], u[0], u[1]);
#pragma unroll
                for (int tm = 0; tm < 4; tm++) MMA16(accG[tm][tn + 1], aF[tm], g[2], g[3]);
#pragma unroll
                for (int tm = 0; tm < 4; tm++) MMA16(accU[tm][tn + 1], aF[tm], u[2], u[3]);
            }
        }
        __syncthreads();
    }

    const int colbase = colExp + bn + wn;
#pragma unroll
    for (int tm = 0; tm < 4; tm++) {
#pragma unroll
        for (int half = 0; half < 2; half++) {
            const int i = bm + wm + tm * 16 + grp + half * 8;
            const int token = tix ? tix[min(i, cnt - 1)] : i;
            const float wgt = scaled ? g_W[token * NEXP + e] : 1.0f;
            const size_t rowoff = (size_t)token * KDOWN;
#pragma unroll
            for (int tn = 0; tn < 4; tn++) {
                float gv0 = accG[tm][tn][half * 2 + 0];
                float gv1 = accG[tm][tn][half * 2 + 1];
                float uv0 = accU[tm][tn][half * 2 + 0];
                float uv1 = accU[tm][tn][half * 2 + 1];
                float h0 = gv0 / (1.f + expf(-gv0)) * uv0 * wgt;
                float h1 = gv1 / (1.f + expf(-gv1)) * uv1 * wgt;
                const int col = colbase + tn * 8 + tI * 2;
                *reinterpret_cast<uint32_t*>(g_H + rowoff + col) =
                    pk_h2(__float2half_rn(h0), __float2half_rn(h1));
            }
        }
    }
}

// ---------------- down fp16 MMA GEMM (combine) --------------------------------------
#define DN_SBUF (2 * TILEB)       // 36864
#define DN_SMEM (2 * DN_SBUF)     // 73728

__global__ __launch_bounds__(256, 2)
void dn_mma(float* __restrict__ out) {
    extern __shared__ __align__(16) char smem[];
    const uint32_t sb = smem_u32(smem);
    const int tid = threadIdx.x;
    const int wid = tid >> 5, lane = tid & 31;
    const int grp = lane >> 2, tI = lane & 3;
    const int wm = (wid >> 2) * 64, wn = (wid & 3) * 32;
    const int bm = blockIdx.y * 128, bn = blockIdx.x * 128;

    const int r0 = tid >> 3, q = tid & 7;
    uint32_t ds[4];
    size_t gA[4], gB[4];
#pragma unroll
    for (int p = 0; p < 4; p++) {
        const int row = r0 + 32 * p;
        ds[p] = row * MSTRIDE + q * 16;
        gA[p] = (size_t)(bm + row) * KDOWN + q * 8;
        gB[p] = (size_t)(bn + row) * KDOWN + q * 8;
    }

    const uint32_t aOff = (lane & 15) * MSTRIDE + (lane >> 4) * 16;
    const uint32_t bOff = (lane & 7) * MSTRIDE + ((lane >> 3) & 1) * 16
                        + (lane >> 4) * 8 * MSTRIDE;

    float acc[4][4][4];
#pragma unroll
    for (int i = 0; i < 4; i++)
#pragma unroll
        for (int j = 0; j < 4; j++)
#pragma unroll
            for (int r = 0; r < 4; r++) acc[i][j][r] = 0.f;

    const int NC = KDOWN / BK;   // 80

    auto issue = [&](int kc, int buf) {
        const int k0 = kc * BK;
        const uint32_t s = sb + buf * DN_SBUF;
#pragma unroll
        for (int p = 0; p < 4; p++) {
            CP16(s + ds[p],         g_H  + gA[p] + k0);
            CP16(s + TILEB + ds[p], g_Bd + gB[p] + k0);
        }
        CP_COMMIT();
    };

    issue(0, 0);
    for (int kc = 0; kc < NC; kc++) {
        const int buf = kc & 1;
        if (kc + 1 < NC) { issue(kc + 1, buf ^ 1); CP_WAIT1(); }
        else             { CP_WAIT0(); }
        __syncthreads();
        const uint32_t s = sb + buf * DN_SBUF;
#pragma unroll
        for (int ks = 0; ks < 4; ks++) {
            uint32_t aF[4][4];
            const uint32_t aBase = s + wm * MSTRIDE + aOff + ks * 32;
#pragma unroll
            for (int tm = 0; tm < 4; tm++)
                LDSM4(aF[tm][0], aF[tm][1], aF[tm][2], aF[tm][3],
                      aBase + tm * 16 * MSTRIDE);
            const uint32_t bB = s + TILEB + wn * MSTRIDE + bOff + ks * 32;
#pragma unroll
            for (int tn2 = 0; tn2 < 2; tn2++) {
                uint32_t b[4];
                LDSM4(b[0], b[1], b[2], b[3], bB + tn2 * 16 * MSTRIDE);
                const int tn = tn2 * 2;
#pragma unroll
                for (int tm = 0; tm < 4; tm++) MMA16(acc[tm][tn],     aF[tm], b[0], b[1]);
#pragma unroll
                for (int tm = 0; tm < 4; tm++) MMA16(acc[tm][tn + 1], aF[tm], b[2], b[3]);
            }
        }
        __syncthreads();
    }

#pragma unroll
    for (int tm = 0; tm < 4; tm++) {
#pragma unroll
        for (int half = 0; half < 2; half++) {
            const int token = bm + wm + tm * 16 + grp + half * 8;
#pragma unroll
            for (int tn = 0; tn < 4; tn++) {
                const int col = bn + wn + tn * 8 + tI * 2;
                float2 v = make_float2(acc[tm][tn][half * 2], acc[tm][tn][half * 2 + 1]);
                *reinterpret_cast<float2*>(out + (size_t)token * DDIM + col) = v;
            }
        }
    }
}

// ---------------- launch ------------------------------------------------------------
extern "C" void kernel_launch(void* const* d_in, const int* in_sizes, int n_in,
                              void* d_out, int out_size) {
    const float* x   = (const float*)d_in[0];
    const float* rw  = (const float*)d_in[1];
    const float* wg  = (const float*)d_in[2];
    const float* wu  = (const float*)d_in[3];
    const float* wd  = (const float*)d_in[4];
    const float* wsg = (const float*)d_in[5];
    const float* wsu = (const float*)d_in[6];
    const float* wsd = (const float*)d_in[7];
    float* out = (float*)d_out;

    void *pX, *pBg, *pBu, *pBsg, *pBsu, *pBd;
    cudaGetSymbolAddress(&pX, g_X);
    cudaGetSymbolAddress(&pBg, g_Bg);   cudaGetSymbolAddress(&pBu, g_Bu);
    cudaGetSymbolAddress(&pBsg, g_Bsg); cudaGetSymbolAddress(&pBsu, g_Bsu);
    cudaGetSymbolAddress(&pBd, g_Bd);

    cudaFuncSetAttribute(gu_mma, cudaFuncAttributeMaxDynamicSharedMemorySize, GU_SMEM);
    cudaFuncSetAttribute(dn_mma, cudaFuncAttributeMaxDynamicSharedMemorySize, DN_SMEM);

    // 1: reset counters
    zcnt<<<1, 32>>>();
    // 2: fused router (scores + topk + complement lists + X fp16)
    router_kernel<<<T_TOK / 4, 128>>>(x, rw, (__half*)pX);
    // 3: zero only unselected (token, expert) H slots
    zeroSel<<<dim3(NEXP, 32), 256>>>();
    // 4-5: weight transpose/convert
    dim3 tb(32, 8);
    prepA<<<dim3(16, 32, 16), tb>>>(wg, wu, (__half*)pBg, (__half*)pBu);
    prepB<<<dim3(32, 32, 11), tb>>>(wsg, wsu, wd, wsd,
        (__half*)pBsg, (__half*)pBsu, (__half*)pBd);
    // 6: merged gate+up (routed z=0..7 gathered, shared z=8 dense)
    gu_mma<<<dim3(FSDIM / 128, T_TOK / 128, NEXP + 1), 256, GU_SMEM>>>(
        (const __half*)pX,
        (const __half*)pBg,  (const __half*)pBu,
        (const __half*)pBsg, (const __half*)pBsu);
    // 7: down + weighted combine + shared add
    dn_mma<<<dim3(DDIM / 128, T_TOK / 128), 256, DN_SMEM>>>(out);
}